// round 1
// baseline (speedup 1.0000x reference)
#include <cuda_runtime.h>
#include <cuda_bf16.h>
#include <math.h>

// Problem constants
#define Bsz 64
#define Nseq 197
#define Dm 768
#define NHd 8
#define HIDm 3072
#define BNROWS (Bsz * Nseq)          // 12608
#define LN_EPS 1e-5f

// ---------------- scratch (static device arrays; no allocations) ----------------
__device__ __align__(256) float g_X1  [BNROWS * Dm];        // ln1 out / x2 reuse
__device__ __align__(256) float g_QKV [BNROWS * 3 * Dm];
__device__ __align__(256) float g_CTX [BNROWS * Dm];
__device__ __align__(256) float g_P   [BNROWS * Dm];        // proj out
__device__ __align__(256) float g_XP  [BNROWS * Dm];        // orth_a out
__device__ __align__(256) float g_XRES[BNROWS * Dm];        // x after 1st residual
__device__ __align__(256) float g_XM  [BNROWS * Dm];        // fc2 out
__device__ __align__(256) float g_H1  [BNROWS * HIDm];      // gelu(fc1)
__device__ __align__(256) float g_H2  [BNROWS * HIDm];      // orth_m out
__device__ __align__(256) float g_Y   [BNROWS * HIDm];      // so8 gate output (shared a/m)
__device__ __align__(256) float g_H3  [BNROWS * HIDm];      // adapter_m out
__device__ __align__(256) float g_E1  [BNROWS];
__device__ __align__(256) float g_E2  [BNROWS];

// ---------------- helpers ----------------
union F2U { unsigned long long u; float2 f; };

__device__ __forceinline__ unsigned long long dup2(float a) {
    unsigned long long r;
    asm("mov.b64 %0, {%1, %1};" : "=l"(r) : "f"(a));
    return r;
}
__device__ __forceinline__ unsigned long long ffma2(unsigned long long a, unsigned long long b,
                                                    unsigned long long c) {
    unsigned long long d;
    asm("fma.rn.f32x2 %0, %1, %2, %3;" : "=l"(d) : "l"(a), "l"(b), "l"(c));
    return d;
}
__device__ __forceinline__ float warp_sum(float v) {
    #pragma unroll
    for (int o = 16; o; o >>= 1) v += __shfl_xor_sync(0xffffffffu, v, o);
    return v;
}
__device__ __forceinline__ float warp_max(float v) {
    #pragma unroll
    for (int o = 16; o; o >>= 1) v = fmaxf(v, __shfl_xor_sync(0xffffffffu, v, o));
    return v;
}
__device__ __forceinline__ float gelu_exact(float v) {
    return v * 0.5f * (1.0f + erff(v * 0.7071067811865476f));
}

// ---------------- LayerNorm (+ optional residual adds) ----------------
// out[row] = LN(X[row]) * g + b  (+ add1[row]) (+ add2[row])
__global__ __launch_bounds__(256) void ln_kernel(
    const float* __restrict__ X, const float* __restrict__ gg, const float* __restrict__ bb,
    const float* __restrict__ add1, const float* __restrict__ add2,
    float* __restrict__ out, int Dg)
{
    size_t row = blockIdx.x;
    const float* x = X + row * (size_t)Dg;
    float s = 0.f, s2 = 0.f;
    for (int i = threadIdx.x; i < Dg; i += 256) {
        float v = x[i];
        s += v; s2 += v * v;
    }
    __shared__ float sh0[8], sh1[8];
    s = warp_sum(s); s2 = warp_sum(s2);
    int w = threadIdx.x >> 5, lane = threadIdx.x & 31;
    if (lane == 0) { sh0[w] = s; sh1[w] = s2; }
    __syncthreads();
    if (threadIdx.x == 0) {
        float a = 0.f, b2 = 0.f;
        #pragma unroll
        for (int i = 0; i < 8; i++) { a += sh0[i]; b2 += sh1[i]; }
        sh0[0] = a; sh1[0] = b2;
    }
    __syncthreads();
    float invD = 1.0f / (float)Dg;
    float mean = sh0[0] * invD;
    float var  = sh1[0] * invD - mean * mean;
    float rstd = rsqrtf(var + LN_EPS);
    for (int i = threadIdx.x; i < Dg; i += 256) {
        float v = (x[i] - mean) * rstd * gg[i] + bb[i];
        if (add1) v += add1[row * (size_t)Dg + i];
        if (add2) v += add2[row * (size_t)Dg + i];
        out[row * (size_t)Dg + i] = v;
    }
}

// ---------------- SGEMM: C[M,Nn] = A[M,K] @ W[Nn,K]^T + bias, optional GELU ----------------
// 128x128 tile, BK=16, 256 threads, 8x8 per thread, packed fp32x2 FMA.
#define TBM 128
#define TBN 128
#define TBK 16
__global__ __launch_bounds__(256) void gemm_kernel(
    const float* __restrict__ A, const float* __restrict__ W,
    const float* __restrict__ bias, float* __restrict__ C,
    int M, int Nn, int K, int do_gelu)
{
    __shared__ float As[TBK][TBM];
    __shared__ float Bs[TBK][TBN];

    int bn = blockIdx.x * TBN;
    int bm = blockIdx.y * TBM;
    int tid = threadIdx.x;
    int tx = tid & 15;       // 0..15 -> 8 cols each
    int ty = tid >> 4;       // 0..15 -> 8 rows each

    unsigned long long acc[8][4];
    #pragma unroll
    for (int i = 0; i < 8; i++)
        #pragma unroll
        for (int j = 0; j < 4; j++) acc[i][j] = 0ull;

    for (int k0 = 0; k0 < K; k0 += TBK) {
        // load tiles: 512 float4 per operand, 2 per thread
        #pragma unroll
        for (int l = 0; l < 2; l++) {
            int f = tid + l * 256;       // 0..511
            int row = f >> 2;            // 0..127
            int c4 = (f & 3) * 4;        // 0,4,8,12
            int gr = bm + row;
            float4 v = make_float4(0.f, 0.f, 0.f, 0.f);
            if (gr < M) v = *(const float4*)(A + (size_t)gr * K + k0 + c4);
            As[c4 + 0][row] = v.x; As[c4 + 1][row] = v.y;
            As[c4 + 2][row] = v.z; As[c4 + 3][row] = v.w;
            int wr = bn + row;           // Nn is always a multiple of 128
            float4 wv = *(const float4*)(W + (size_t)wr * K + k0 + c4);
            Bs[c4 + 0][row] = wv.x; Bs[c4 + 1][row] = wv.y;
            Bs[c4 + 2][row] = wv.z; Bs[c4 + 3][row] = wv.w;
        }
        __syncthreads();

        #pragma unroll
        for (int k = 0; k < TBK; k++) {
            float4 a0 = *(const float4*)&As[k][ty * 8];
            float4 a1 = *(const float4*)&As[k][ty * 8 + 4];
            const unsigned long long* bp = (const unsigned long long*)&Bs[k][tx * 8];
            unsigned long long bb0 = bp[0], bb1 = bp[1], bb2 = bp[2], bb3 = bp[3];
            unsigned long long aa[8];
            aa[0] = dup2(a0.x); aa[1] = dup2(a0.y); aa[2] = dup2(a0.z); aa[3] = dup2(a0.w);
            aa[4] = dup2(a1.x); aa[5] = dup2(a1.y); aa[6] = dup2(a1.z); aa[7] = dup2(a1.w);
            #pragma unroll
            for (int i = 0; i < 8; i++) {
                acc[i][0] = ffma2(aa[i], bb0, acc[i][0]);
                acc[i][1] = ffma2(aa[i], bb1, acc[i][1]);
                acc[i][2] = ffma2(aa[i], bb2, acc[i][2]);
                acc[i][3] = ffma2(aa[i], bb3, acc[i][3]);
            }
        }
        __syncthreads();
    }

    // epilogue
    #pragma unroll
    for (int i = 0; i < 8; i++) {
        int gr = bm + ty * 8 + i;
        if (gr >= M) continue;
        float* crow = C + (size_t)gr * Nn + bn + tx * 8;
        #pragma unroll
        for (int j = 0; j < 4; j++) {
            F2U u; u.u = acc[i][j];
            int gc = bn + tx * 8 + 2 * j;
            u.f.x += bias[gc];
            u.f.y += bias[gc + 1];
            if (do_gelu) { u.f.x = gelu_exact(u.f.x); u.f.y = gelu_exact(u.f.y); }
            *(float2*)(crow + 2 * j) = u.f;
        }
    }
}

// ---------------- fused attention: one block per (b, h) ----------------
#define HD 96
#define KPAD 97
#define ATTN_SMEM ((Nseq * KPAD * 2 + 8 * HD + 8 * 204) * 4)
__global__ __launch_bounds__(256) void attn_kernel(
    const float* __restrict__ QKV, float* __restrict__ CTX)
{
    extern __shared__ float sm[];
    float* Ks = sm;                          // 197*97
    float* Vs = Ks + Nseq * KPAD;            // 197*97
    float* qb = Vs + Nseq * KPAD;            // 8*96
    float* ps = qb + 8 * HD;                 // 8*204

    int bh = blockIdx.x;
    int b = bh / NHd, h = bh % NHd;
    int tid = threadIdx.x, lane = tid & 31, w = tid >> 5;

    for (int idx = tid; idx < Nseq * HD; idx += 256) {
        int r = idx / HD, c = idx - r * HD;
        size_t g = (size_t)(b * Nseq + r) * (3 * Dm) + h * HD + c;
        Ks[r * KPAD + c] = QKV[g + Dm];
        Vs[r * KPAD + c] = QKV[g + 2 * Dm];
    }
    __syncthreads();

    const float scl = rsqrtf((float)HD);
    for (int q = w; q < Nseq; q += 8) {
        for (int d2 = lane; d2 < HD; d2 += 32)
            qb[w * HD + d2] = QKV[(size_t)(b * Nseq + q) * (3 * Dm) + h * HD + d2];
        __syncwarp();

        float s[7];
        float mx = -1e30f;
        #pragma unroll
        for (int jj = 0; jj < 7; jj++) {
            int j = lane + jj * 32;
            float acc = -1e30f;
            if (j < Nseq) {
                acc = 0.f;
                const float* kr = &Ks[j * KPAD];
                const float* qr = &qb[w * HD];
                #pragma unroll 4
                for (int d2 = 0; d2 < HD; d2++) acc += qr[d2] * kr[d2];
                acc *= scl;
            }
            s[jj] = acc;
            mx = fmaxf(mx, acc);
        }
        mx = warp_max(mx);
        float sum = 0.f;
        #pragma unroll
        for (int jj = 0; jj < 7; jj++) {
            int j = lane + jj * 32;
            if (j < Nseq) {
                float e = expf(s[jj] - mx);
                ps[w * 204 + j] = e;
                sum += e;
            }
        }
        sum = warp_sum(sum);
        float inv = 1.0f / sum;
        __syncwarp();

        for (int d2 = lane; d2 < HD; d2 += 32) {
            float acc = 0.f;
            const float* pw = &ps[w * 204];
            for (int j = 0; j < Nseq; j++) acc += pw[j] * Vs[j * KPAD + d2];
            CTX[(size_t)(b * Nseq + q) * Dm + h * HD + d2] = acc * inv;
        }
        __syncwarp();
    }
}

// ---------------- SO8 gate: rotate first 8 of each hd-block, add base, compute err ----------------
__global__ __launch_bounds__(256) void so8_kernel(
    const float* __restrict__ XP, const float* __restrict__ base,
    const float* __restrict__ eps, const float* __restrict__ scale_p,
    float* __restrict__ Y, float* __restrict__ err, int Dg, int hd)
{
    size_t row = blockIdx.x;
    __shared__ float errsum[8];
    if (threadIdx.x < 8) errsum[threadIdx.x] = 0.f;
    __syncthreads();
    float scale = scale_p[0];
    const float* xp = XP + row * (size_t)Dg;
    const float* bs = base + row * (size_t)Dg;
    float* y = Y + row * (size_t)Dg;

    for (int i = threadIdx.x; i < Dg; i += 256) {
        int head = i / hd;
        int pos = i - head * hd;
        float v;
        if (pos < 8) {
            int pr = pos >> 1;
            float ang = eps[row * 32 + head * 4 + pr] * scale;
            float sn, c;
            sincosf(ang, &sn, &c);
            float e = xp[head * hd + 2 * pr];
            float o = xp[head * hd + 2 * pr + 1];
            float rot, orig;
            if (pos & 1) { rot = e * sn + o * c; orig = o; }
            else         { rot = e * c - o * sn; orig = e; }
            float d = rot - orig;
            atomicAdd(&errsum[head], d * d);
            v = rot;
        } else {
            v = xp[i];
        }
        y[i] = v + bs[i];
    }
    __syncthreads();
    if (threadIdx.x == 0) {
        float e = 0.f;
        #pragma unroll
        for (int hh = 0; hh < 8; hh++) e += sqrtf(errsum[hh]);
        err[row] = e * 0.125f;
    }
}

// ---------------- final: out = [xres + xm (BN*D), e1 + e2 (BN)] ----------------
__global__ __launch_bounds__(256) void final_kernel(
    const float* __restrict__ xres, const float* __restrict__ xm,
    const float* __restrict__ e1, const float* __restrict__ e2,
    float* __restrict__ out)
{
    size_t idx = (size_t)blockIdx.x * 256 + threadIdx.x;
    const size_t total = (size_t)BNROWS * Dm;
    if (idx < total) out[idx] = xres[idx] + xm[idx];
    if (idx < BNROWS) out[total + idx] = e1[idx] + e2[idx];
}

// ---------------- launch ----------------
extern "C" void kernel_launch(void* const* d_in, const int* in_sizes, int n_in,
                              void* d_out, int out_size)
{
    const float* x       = (const float*)d_in[0];
    const float* qkv_w   = (const float*)d_in[1];
    const float* qkv_b   = (const float*)d_in[2];
    const float* proj_w  = (const float*)d_in[3];
    const float* proj_b  = (const float*)d_in[4];
    const float* norm1_g = (const float*)d_in[5];
    const float* norm1_b = (const float*)d_in[6];
    const float* norm2_g = (const float*)d_in[7];
    const float* norm2_b = (const float*)d_in[8];
    const float* orth_w_a = (const float*)d_in[9];
    const float* orth_b_a = (const float*)d_in[10];
    const float* scale_a  = (const float*)d_in[11];
    const float* ln_g_a   = (const float*)d_in[12];
    const float* ln_b_a   = (const float*)d_in[13];
    const float* orth_w_m = (const float*)d_in[14];
    const float* orth_b_m = (const float*)d_in[15];
    const float* scale_m  = (const float*)d_in[16];
    const float* ln_g_m   = (const float*)d_in[17];
    const float* ln_b_m   = (const float*)d_in[18];
    const float* fc1_w    = (const float*)d_in[19];
    const float* fc1_b    = (const float*)d_in[20];
    const float* fc2_w    = (const float*)d_in[21];
    const float* fc2_b    = (const float*)d_in[22];
    const float* eps_a    = (const float*)d_in[23];
    const float* eps_m    = (const float*)d_in[24];
    float* out = (float*)d_out;

    float *X1, *QKV, *CTX, *P, *XP, *XRES, *XM, *H1, *H2, *Y, *H3, *E1, *E2;
    cudaGetSymbolAddress((void**)&X1,   g_X1);
    cudaGetSymbolAddress((void**)&QKV,  g_QKV);
    cudaGetSymbolAddress((void**)&CTX,  g_CTX);
    cudaGetSymbolAddress((void**)&P,    g_P);
    cudaGetSymbolAddress((void**)&XP,   g_XP);
    cudaGetSymbolAddress((void**)&XRES, g_XRES);
    cudaGetSymbolAddress((void**)&XM,   g_XM);
    cudaGetSymbolAddress((void**)&H1,   g_H1);
    cudaGetSymbolAddress((void**)&H2,   g_H2);
    cudaGetSymbolAddress((void**)&Y,    g_Y);
    cudaGetSymbolAddress((void**)&H3,   g_H3);
    cudaGetSymbolAddress((void**)&E1,   g_E1);
    cudaGetSymbolAddress((void**)&E2,   g_E2);

    cudaFuncSetAttribute(attn_kernel, cudaFuncAttributeMaxDynamicSharedMemorySize, ATTN_SMEM);

    const int MROWS = BNROWS;               // 12608
    const int GY = (MROWS + TBM - 1) / TBM; // 99
    dim3 blk(256);

    // 1) x1 = LN1(x)
    ln_kernel<<<MROWS, blk>>>(x, norm1_g, norm1_b, nullptr, nullptr, X1, Dm);
    // 2) qkv = x1 @ qkv_w^T + qkv_b
    gemm_kernel<<<dim3(3 * Dm / TBN, GY), blk>>>(X1, qkv_w, qkv_b, QKV, MROWS, 3 * Dm, Dm, 0);
    // 3) attention -> ctx
    attn_kernel<<<Bsz * NHd, blk, ATTN_SMEM>>>(QKV, CTX);
    // 4) proj
    gemm_kernel<<<dim3(Dm / TBN, GY), blk>>>(CTX, proj_w, proj_b, P, MROWS, Dm, Dm, 0);
    // 5) adapter A: xp = P @ orth_w_a^T + b
    gemm_kernel<<<dim3(Dm / TBN, GY), blk>>>(P, orth_w_a, orth_b_a, XP, MROWS, Dm, Dm, 0);
    // 6) so8 gate A: Y = rot(xp) + P, err1
    so8_kernel<<<MROWS, blk>>>(XP, P, eps_a, scale_a, Y, E1, Dm, Dm / 8);
    // 7) xres = LN(Y)*g+b + P + x
    ln_kernel<<<MROWS, blk>>>(Y, ln_g_a, ln_b_a, P, x, XRES, Dm);
    // 8) x2 = LN2(xres)  (reuse X1)
    ln_kernel<<<MROWS, blk>>>(XRES, norm2_g, norm2_b, nullptr, nullptr, X1, Dm);
    // 9) h1 = gelu(x2 @ fc1^T + b)
    gemm_kernel<<<dim3(HIDm / TBN, GY), blk>>>(X1, fc1_w, fc1_b, H1, MROWS, HIDm, Dm, 1);
    // 10) adapter M: h2 = h1 @ orth_w_m^T + b   (the 238-GFLOP GEMM)
    gemm_kernel<<<dim3(HIDm / TBN, GY), blk>>>(H1, orth_w_m, orth_b_m, H2, MROWS, HIDm, HIDm, 0);
    // 11) so8 gate M: Y = rot(h2) + h1, err2
    so8_kernel<<<MROWS, blk>>>(H2, H1, eps_m, scale_m, Y, E2, HIDm, HIDm / 8);
    // 12) h3 = LN(Y)*g+b + h1
    ln_kernel<<<MROWS, blk>>>(Y, ln_g_m, ln_b_m, H1, nullptr, H3, HIDm);
    // 13) xm = h3 @ fc2^T + b
    gemm_kernel<<<dim3(Dm / TBN, GY), blk>>>(H3, fc2_w, fc2_b, XM, MROWS, Dm, HIDm, 0);
    // 14) out = concat(xres + xm, e1 + e2)
    final_kernel<<<((size_t)MROWS * Dm + 255) / 256, blk>>>(XRES, XM, E1, E2, out);
}

// round 4
// speedup vs baseline: 2.3914x; 2.3914x over previous
#include <cuda_runtime.h>
#include <cuda_bf16.h>
#include <math.h>
#include <stdint.h>

// Problem constants
#define Bsz 64
#define Nseq 197
#define Dm 768
#define NHd 8
#define HIDm 3072
#define BNROWS (Bsz * Nseq)          // 12608
#define LN_EPS 1e-5f

// ---------------- scratch (static device arrays; no allocations) ----------------
__device__ __align__(256) float g_X1  [BNROWS * Dm];
__device__ __align__(256) float g_QKV [BNROWS * 3 * Dm];
__device__ __align__(256) float g_CTX [BNROWS * Dm];
__device__ __align__(256) float g_P   [BNROWS * Dm];
__device__ __align__(256) float g_XP  [BNROWS * Dm];
__device__ __align__(256) float g_XRES[BNROWS * Dm];
__device__ __align__(256) float g_XM  [BNROWS * Dm];
__device__ __align__(256) float g_H1  [BNROWS * HIDm];
__device__ __align__(256) float g_H2  [BNROWS * HIDm];
__device__ __align__(256) float g_Y   [BNROWS * HIDm];
__device__ __align__(256) float g_H3  [BNROWS * HIDm];
__device__ __align__(256) float g_E1  [BNROWS];
__device__ __align__(256) float g_E2  [BNROWS];

// ---------------- helpers ----------------
__device__ __forceinline__ uint32_t cvt_tf32(float f) {
    uint32_t u;
    asm("cvt.rna.tf32.f32 %0, %1;" : "=r"(u) : "f"(f));
    return u;
}
__device__ __forceinline__ void mma_tf32_16x8x8(float* d, const uint32_t* a, const uint32_t* b) {
    asm volatile("mma.sync.aligned.m16n8k8.row.col.f32.tf32.tf32.f32 "
        "{%0,%1,%2,%3}, {%4,%5,%6,%7}, {%8,%9}, {%0,%1,%2,%3};"
        : "+f"(d[0]), "+f"(d[1]), "+f"(d[2]), "+f"(d[3])
        : "r"(a[0]), "r"(a[1]), "r"(a[2]), "r"(a[3]), "r"(b[0]), "r"(b[1]));
}
__device__ __forceinline__ float warp_sum(float v) {
    #pragma unroll
    for (int o = 16; o; o >>= 1) v += __shfl_xor_sync(0xffffffffu, v, o);
    return v;
}
__device__ __forceinline__ float warp_max(float v) {
    #pragma unroll
    for (int o = 16; o; o >>= 1) v = fmaxf(v, __shfl_xor_sync(0xffffffffu, v, o));
    return v;
}
__device__ __forceinline__ float gelu_exact(float v) {
    return v * 0.5f * (1.0f + erff(v * 0.7071067811865476f));
}

// ---------------- tf32 mma.sync GEMM: C[M,Nn] = A[M,K] @ W[Nn,K]^T + bias (+GELU) ----
// BM=128, BN=128, BK=32. 256 threads = 8 warps (2 x 4): each warp 64x32.
// Per warp: 4 m-tiles (16) x 4 n-tiles (8), K in steps of 8.
// SMEM padded stride 36 floats -> conflict-free fragment LDS.
#define ASTR 36
#define BUF_FLOATS (128 * ASTR)                  // 4608 floats per operand tile
#define GEMM_SMEM_BYTES (2 * 2 * BUF_FLOATS * 4) // 73728 bytes

__global__ void __launch_bounds__(256, 2) gemm_tc(
    const float* __restrict__ A, const float* __restrict__ W,
    const float* __restrict__ bias, float* __restrict__ C,
    int M, int Nn, int K, int do_gelu)
{
    extern __shared__ float sm[];
    // buffer b: A at sm + b*2*BUF, B at sm + b*2*BUF + BUF

    int tid = threadIdx.x;
    int wid = tid >> 5, lane = tid & 31;
    int gid = lane >> 2, tig = lane & 3;
    int wm = (wid & 1) * 64;          // warp m offset in tile
    int wn = (wid >> 1) * 32;         // warp n offset in tile
    int bm = blockIdx.y * 128, bn = blockIdx.x * 128;

    // per-thread gmem load coords (4 float4 per operand)
    int ldrow[4], ldc4[4];
    #pragma unroll
    for (int l = 0; l < 4; l++) {
        int id = tid + l * 256;       // 0..1023
        ldrow[l] = id >> 3;           // 0..127
        ldc4[l] = (id & 7) << 2;      // 0,4,..28
    }

    float acc[4][4][4];
    #pragma unroll
    for (int mt = 0; mt < 4; mt++)
        #pragma unroll
        for (int nt = 0; nt < 4; nt++)
            #pragma unroll
            for (int r = 0; r < 4; r++) acc[mt][nt][r] = 0.f;

    float4 ar[4], br[4];
    // prologue: load tile 0
    #pragma unroll
    for (int l = 0; l < 4; l++) {
        int gr = bm + ldrow[l];
        ar[l] = make_float4(0.f, 0.f, 0.f, 0.f);
        if (gr < M) ar[l] = *(const float4*)(A + (size_t)gr * K + ldc4[l]);
        br[l] = *(const float4*)(W + (size_t)(bn + ldrow[l]) * K + ldc4[l]);
    }
    {
        float* sa = sm;
        float* sb = sm + BUF_FLOATS;
        #pragma unroll
        for (int l = 0; l < 4; l++) {
            uint4 t;
            t.x = cvt_tf32(ar[l].x); t.y = cvt_tf32(ar[l].y);
            t.z = cvt_tf32(ar[l].z); t.w = cvt_tf32(ar[l].w);
            *(uint4*)(sa + ldrow[l] * ASTR + ldc4[l]) = t;
            t.x = cvt_tf32(br[l].x); t.y = cvt_tf32(br[l].y);
            t.z = cvt_tf32(br[l].z); t.w = cvt_tf32(br[l].w);
            *(uint4*)(sb + ldrow[l] * ASTR + ldc4[l]) = t;
        }
    }
    __syncthreads();

    int NC = K >> 5;
    for (int c = 0; c < NC; c++) {
        // issue gmem loads for next tile (latency overlapped with compute)
        if (c + 1 < NC) {
            int k0 = (c + 1) << 5;
            #pragma unroll
            for (int l = 0; l < 4; l++) {
                int gr = bm + ldrow[l];
                ar[l] = make_float4(0.f, 0.f, 0.f, 0.f);
                if (gr < M) ar[l] = *(const float4*)(A + (size_t)gr * K + k0 + ldc4[l]);
                br[l] = *(const float4*)(W + (size_t)(bn + ldrow[l]) * K + k0 + ldc4[l]);
            }
        }

        const uint32_t* As = (const uint32_t*)(sm + (c & 1) * 2 * BUF_FLOATS);
        const uint32_t* Bs = As + BUF_FLOATS;
        #pragma unroll
        for (int kk = 0; kk < 4; kk++) {
            int k = kk * 8;
            uint32_t af[4][4], bf[4][2];
            #pragma unroll
            for (int mt = 0; mt < 4; mt++) {
                int r0 = wm + mt * 16 + gid;
                af[mt][0] = As[r0 * ASTR + k + tig];
                af[mt][1] = As[(r0 + 8) * ASTR + k + tig];
                af[mt][2] = As[r0 * ASTR + k + tig + 4];
                af[mt][3] = As[(r0 + 8) * ASTR + k + tig + 4];
            }
            #pragma unroll
            for (int nt = 0; nt < 4; nt++) {
                int n0 = wn + nt * 8 + gid;
                bf[nt][0] = Bs[n0 * ASTR + k + tig];
                bf[nt][1] = Bs[n0 * ASTR + k + tig + 4];
            }
            #pragma unroll
            for (int mt = 0; mt < 4; mt++)
                #pragma unroll
                for (int nt = 0; nt < 4; nt++)
                    mma_tf32_16x8x8(acc[mt][nt], af[mt], bf[nt]);
        }

        if (c + 1 < NC) {
            float* sa = sm + ((c + 1) & 1) * 2 * BUF_FLOATS;
            float* sb = sa + BUF_FLOATS;
            #pragma unroll
            for (int l = 0; l < 4; l++) {
                uint4 t;
                t.x = cvt_tf32(ar[l].x); t.y = cvt_tf32(ar[l].y);
                t.z = cvt_tf32(ar[l].z); t.w = cvt_tf32(ar[l].w);
                *(uint4*)(sa + ldrow[l] * ASTR + ldc4[l]) = t;
                t.x = cvt_tf32(br[l].x); t.y = cvt_tf32(br[l].y);
                t.z = cvt_tf32(br[l].z); t.w = cvt_tf32(br[l].w);
                *(uint4*)(sb + ldrow[l] * ASTR + ldc4[l]) = t;
            }
        }
        __syncthreads();
    }

    // epilogue
    #pragma unroll
    for (int mt = 0; mt < 4; mt++) {
        int row0 = bm + wm + mt * 16 + gid;
        #pragma unroll
        for (int half = 0; half < 2; half++) {
            int row = row0 + half * 8;
            if (row >= M) continue;
            float* crow = C + (size_t)row * Nn;
            #pragma unroll
            for (int nt = 0; nt < 4; nt++) {
                int col = bn + wn + nt * 8 + tig * 2;
                float2 o;
                o.x = acc[mt][nt][half * 2 + 0] + bias[col];
                o.y = acc[mt][nt][half * 2 + 1] + bias[col + 1];
                if (do_gelu) { o.x = gelu_exact(o.x); o.y = gelu_exact(o.y); }
                *(float2*)(crow + col) = o;
            }
        }
    }
}

// ---------------- LayerNorm (+ optional residual adds) ----------------
__global__ __launch_bounds__(256) void ln_kernel(
    const float* __restrict__ X, const float* __restrict__ gg, const float* __restrict__ bb,
    const float* __restrict__ add1, const float* __restrict__ add2,
    float* __restrict__ out, int Dg)
{
    size_t row = blockIdx.x;
    const float* x = X + row * (size_t)Dg;
    float s = 0.f, s2 = 0.f;
    for (int i = threadIdx.x; i < Dg; i += 256) {
        float v = x[i];
        s += v; s2 += v * v;
    }
    __shared__ float sh0[8], sh1[8];
    s = warp_sum(s); s2 = warp_sum(s2);
    int w = threadIdx.x >> 5, lane = threadIdx.x & 31;
    if (lane == 0) { sh0[w] = s; sh1[w] = s2; }
    __syncthreads();
    if (threadIdx.x == 0) {
        float a = 0.f, b2 = 0.f;
        #pragma unroll
        for (int i = 0; i < 8; i++) { a += sh0[i]; b2 += sh1[i]; }
        sh0[0] = a; sh1[0] = b2;
    }
    __syncthreads();
    float invD = 1.0f / (float)Dg;
    float mean = sh0[0] * invD;
    float var  = sh1[0] * invD - mean * mean;
    float rstd = rsqrtf(var + LN_EPS);
    for (int i = threadIdx.x; i < Dg; i += 256) {
        float v = (x[i] - mean) * rstd * gg[i] + bb[i];
        if (add1) v += add1[row * (size_t)Dg + i];
        if (add2) v += add2[row * (size_t)Dg + i];
        out[row * (size_t)Dg + i] = v;
    }
}

// ---------------- fused attention: one block per (b, h) ----------------
#define HD 96
#define KPAD 97
#define ATTN_SMEM ((Nseq * KPAD * 2 + 8 * HD + 8 * 204) * 4)
__global__ __launch_bounds__(256) void attn_kernel(
    const float* __restrict__ QKV, float* __restrict__ CTX)
{
    extern __shared__ float smf[];
    float* Ks = smf;
    float* Vs = Ks + Nseq * KPAD;
    float* qb = Vs + Nseq * KPAD;
    float* ps = qb + 8 * HD;

    int bh = blockIdx.x;
    int b = bh / NHd, h = bh % NHd;
    int tid = threadIdx.x, lane = tid & 31, w = tid >> 5;

    for (int idx = tid; idx < Nseq * HD; idx += 256) {
        int r = idx / HD, c = idx - r * HD;
        size_t g = (size_t)(b * Nseq + r) * (3 * Dm) + h * HD + c;
        Ks[r * KPAD + c] = QKV[g + Dm];
        Vs[r * KPAD + c] = QKV[g + 2 * Dm];
    }
    __syncthreads();

    const float scl = rsqrtf((float)HD);
    for (int q = w; q < Nseq; q += 8) {
        for (int d2 = lane; d2 < HD; d2 += 32)
            qb[w * HD + d2] = QKV[(size_t)(b * Nseq + q) * (3 * Dm) + h * HD + d2];
        __syncwarp();

        float s[7];
        float mx = -1e30f;
        #pragma unroll
        for (int jj = 0; jj < 7; jj++) {
            int j = lane + jj * 32;
            float acc = -1e30f;
            if (j < Nseq) {
                acc = 0.f;
                const float* kr = &Ks[j * KPAD];
                const float* qr = &qb[w * HD];
                #pragma unroll 4
                for (int d2 = 0; d2 < HD; d2++) acc += qr[d2] * kr[d2];
                acc *= scl;
            }
            s[jj] = acc;
            mx = fmaxf(mx, acc);
        }
        mx = warp_max(mx);
        float sum = 0.f;
        #pragma unroll
        for (int jj = 0; jj < 7; jj++) {
            int j = lane + jj * 32;
            if (j < Nseq) {
                float e = expf(s[jj] - mx);
                ps[w * 204 + j] = e;
                sum += e;
            }
        }
        sum = warp_sum(sum);
        float inv = 1.0f / sum;
        __syncwarp();

        for (int d2 = lane; d2 < HD; d2 += 32) {
            float acc = 0.f;
            const float* pw = &ps[w * 204];
            for (int j = 0; j < Nseq; j++) acc += pw[j] * Vs[j * KPAD + d2];
            CTX[(size_t)(b * Nseq + q) * Dm + h * HD + d2] = acc * inv;
        }
        __syncwarp();
    }
}

// ---------------- SO8 gate ----------------
__global__ __launch_bounds__(256) void so8_kernel(
    const float* __restrict__ XP, const float* __restrict__ base,
    const float* __restrict__ eps, const float* __restrict__ scale_p,
    float* __restrict__ Y, float* __restrict__ err, int Dg, int hd)
{
    size_t row = blockIdx.x;
    __shared__ float errsum[8];
    if (threadIdx.x < 8) errsum[threadIdx.x] = 0.f;
    __syncthreads();
    float scale = scale_p[0];
    const float* xp = XP + row * (size_t)Dg;
    const float* bs = base + row * (size_t)Dg;
    float* y = Y + row * (size_t)Dg;

    for (int i = threadIdx.x; i < Dg; i += 256) {
        int head = i / hd;
        int pos = i - head * hd;
        float v;
        if (pos < 8) {
            int pr = pos >> 1;
            float ang = eps[row * 32 + head * 4 + pr] * scale;
            float sn, c;
            sincosf(ang, &sn, &c);
            float e = xp[head * hd + 2 * pr];
            float o = xp[head * hd + 2 * pr + 1];
            float rot, orig;
            if (pos & 1) { rot = e * sn + o * c; orig = o; }
            else         { rot = e * c - o * sn; orig = e; }
            float d = rot - orig;
            atomicAdd(&errsum[head], d * d);
            v = rot;
        } else {
            v = xp[i];
        }
        y[i] = v + bs[i];
    }
    __syncthreads();
    if (threadIdx.x == 0) {
        float e = 0.f;
        #pragma unroll
        for (int hh = 0; hh < 8; hh++) e += sqrtf(errsum[hh]);
        err[row] = e * 0.125f;
    }
}

// ---------------- final concat ----------------
__global__ __launch_bounds__(256) void final_kernel(
    const float* __restrict__ xres, const float* __restrict__ xm,
    const float* __restrict__ e1, const float* __restrict__ e2,
    float* __restrict__ out)
{
    size_t idx = (size_t)blockIdx.x * 256 + threadIdx.x;
    const size_t total = (size_t)BNROWS * Dm;
    if (idx < total) out[idx] = xres[idx] + xm[idx];
    if (idx < BNROWS) out[total + idx] = e1[idx] + e2[idx];
}

// ---------------- launch ----------------
extern "C" void kernel_launch(void* const* d_in, const int* in_sizes, int n_in,
                              void* d_out, int out_size)
{
    const float* x       = (const float*)d_in[0];
    const float* qkv_w   = (const float*)d_in[1];
    const float* qkv_b   = (const float*)d_in[2];
    const float* proj_w  = (const float*)d_in[3];
    const float* proj_b  = (const float*)d_in[4];
    const float* norm1_g = (const float*)d_in[5];
    const float* norm1_b = (const float*)d_in[6];
    const float* norm2_g = (const float*)d_in[7];
    const float* norm2_b = (const float*)d_in[8];
    const float* orth_w_a = (const float*)d_in[9];
    const float* orth_b_a = (const float*)d_in[10];
    const float* scale_a  = (const float*)d_in[11];
    const float* ln_g_a   = (const float*)d_in[12];
    const float* ln_b_a   = (const float*)d_in[13];
    const float* orth_w_m = (const float*)d_in[14];
    const float* orth_b_m = (const float*)d_in[15];
    const float* scale_m  = (const float*)d_in[16];
    const float* ln_g_m   = (const float*)d_in[17];
    const float* ln_b_m   = (const float*)d_in[18];
    const float* fc1_w    = (const float*)d_in[19];
    const float* fc1_b    = (const float*)d_in[20];
    const float* fc2_w    = (const float*)d_in[21];
    const float* fc2_b    = (const float*)d_in[22];
    const float* eps_a    = (const float*)d_in[23];
    const float* eps_m    = (const float*)d_in[24];
    float* out = (float*)d_out;

    float *X1, *QKV, *CTX, *P, *XP, *XRES, *XM, *H1, *H2, *Y, *H3, *E1, *E2;
    cudaGetSymbolAddress((void**)&X1,   g_X1);
    cudaGetSymbolAddress((void**)&QKV,  g_QKV);
    cudaGetSymbolAddress((void**)&CTX,  g_CTX);
    cudaGetSymbolAddress((void**)&P,    g_P);
    cudaGetSymbolAddress((void**)&XP,   g_XP);
    cudaGetSymbolAddress((void**)&XRES, g_XRES);
    cudaGetSymbolAddress((void**)&XM,   g_XM);
    cudaGetSymbolAddress((void**)&H1,   g_H1);
    cudaGetSymbolAddress((void**)&H2,   g_H2);
    cudaGetSymbolAddress((void**)&Y,    g_Y);
    cudaGetSymbolAddress((void**)&H3,   g_H3);
    cudaGetSymbolAddress((void**)&E1,   g_E1);
    cudaGetSymbolAddress((void**)&E2,   g_E2);

    cudaFuncSetAttribute(attn_kernel, cudaFuncAttributeMaxDynamicSharedMemorySize, ATTN_SMEM);
    cudaFuncSetAttribute(gemm_tc, cudaFuncAttributeMaxDynamicSharedMemorySize, GEMM_SMEM_BYTES);

    const int MROWS = BNROWS;
    const int GY = (MROWS + 127) / 128;    // 99
    dim3 blk(256);

    // 1) x1 = LN1(x)
    ln_kernel<<<MROWS, blk>>>(x, norm1_g, norm1_b, nullptr, nullptr, X1, Dm);
    // 2) qkv = x1 @ qkv_w^T + qkv_b
    gemm_tc<<<dim3(3 * Dm / 128, GY), blk, GEMM_SMEM_BYTES>>>(X1, qkv_w, qkv_b, QKV, MROWS, 3 * Dm, Dm, 0);
    // 3) attention -> ctx
    attn_kernel<<<Bsz * NHd, blk, ATTN_SMEM>>>(QKV, CTX);
    // 4) proj
    gemm_tc<<<dim3(Dm / 128, GY), blk, GEMM_SMEM_BYTES>>>(CTX, proj_w, proj_b, P, MROWS, Dm, Dm, 0);
    // 5) adapter A: xp = P @ orth_w_a^T + b
    gemm_tc<<<dim3(Dm / 128, GY), blk, GEMM_SMEM_BYTES>>>(P, orth_w_a, orth_b_a, XP, MROWS, Dm, Dm, 0);
    // 6) so8 gate A
    so8_kernel<<<MROWS, blk>>>(XP, P, eps_a, scale_a, Y, E1, Dm, Dm / 8);
    // 7) xres = LN(Y)*g+b + P + x
    ln_kernel<<<MROWS, blk>>>(Y, ln_g_a, ln_b_a, P, x, XRES, Dm);
    // 8) x2 = LN2(xres)
    ln_kernel<<<MROWS, blk>>>(XRES, norm2_g, norm2_b, nullptr, nullptr, X1, Dm);
    // 9) h1 = gelu(x2 @ fc1^T + b)
    gemm_tc<<<dim3(HIDm / 128, GY), blk, GEMM_SMEM_BYTES>>>(X1, fc1_w, fc1_b, H1, MROWS, HIDm, Dm, 1);
    // 10) h2 = h1 @ orth_w_m^T + b
    gemm_tc<<<dim3(HIDm / 128, GY), blk, GEMM_SMEM_BYTES>>>(H1, orth_w_m, orth_b_m, H2, MROWS, HIDm, HIDm, 0);
    // 11) so8 gate M
    so8_kernel<<<MROWS, blk>>>(H2, H1, eps_m, scale_m, Y, E2, HIDm, HIDm / 8);
    // 12) h3 = LN(Y)*g+b + h1
    ln_kernel<<<MROWS, blk>>>(Y, ln_g_m, ln_b_m, H1, nullptr, H3, HIDm);
    // 13) xm = h3 @ fc2^T + b
    gemm_tc<<<dim3(Dm / 128, GY), blk, GEMM_SMEM_BYTES>>>(H3, fc2_w, fc2_b, XM, MROWS, Dm, HIDm, 0);
    // 14) out
    final_kernel<<<((size_t)MROWS * Dm + 255) / 256, blk>>>(XRES, XM, E1, E2, out);
}

// round 6
// speedup vs baseline: 3.4064x; 1.4245x over previous
#include <cuda_runtime.h>
#include <cuda_bf16.h>
#include <math.h>
#include <stdint.h>

// Problem constants
#define Bsz 64
#define Nseq 197
#define Dm 768
#define NHd 8
#define HIDm 3072
#define BNROWS (Bsz * Nseq)          // 12608
#define LN_EPS 1e-5f

// ---------------- scratch (static device arrays; no allocations) ----------------
__device__ __align__(256) float g_X1  [BNROWS * Dm];
__device__ __align__(256) float g_QKV [BNROWS * 3 * Dm];
__device__ __align__(256) float g_CTX [BNROWS * Dm];
__device__ __align__(256) float g_P   [BNROWS * Dm];
__device__ __align__(256) float g_XP  [BNROWS * Dm];
__device__ __align__(256) float g_XRES[BNROWS * Dm];
__device__ __align__(256) float g_XM  [BNROWS * Dm];
__device__ __align__(256) float g_H1  [BNROWS * HIDm];
__device__ __align__(256) float g_H2  [BNROWS * HIDm];
__device__ __align__(256) float g_H3  [BNROWS * HIDm];
__device__ __align__(256) float g_E1  [BNROWS];
__device__ __align__(256) float g_E2  [BNROWS];
// tf32-rounded weights
__device__ __align__(256) float g_WQKV [3 * Dm * Dm];
__device__ __align__(256) float g_WPROJ[Dm * Dm];
__device__ __align__(256) float g_WOA  [Dm * Dm];
__device__ __align__(256) float g_WOM  [HIDm * HIDm];
__device__ __align__(256) float g_WF1  [HIDm * Dm];
__device__ __align__(256) float g_WF2  [Dm * HIDm];

// ---------------- helpers ----------------
__device__ __forceinline__ uint32_t smem_u32(const void* p) {
    uint32_t a;
    asm("{ .reg .u64 t; cvta.to.shared.u64 t, %1; cvt.u32.u64 %0, t; }" : "=r"(a) : "l"(p));
    return a;
}
__device__ __forceinline__ uint32_t cvt_tf32(float f) {
    uint32_t u;
    asm("cvt.rna.tf32.f32 %0, %1;" : "=r"(u) : "f"(f));
    return u;
}
__device__ __forceinline__ float round_tf32f(float f) {
    return __uint_as_float(cvt_tf32(f));
}
__device__ __forceinline__ void mma_tf32_16x8x8(float* d, const uint32_t* a, const uint32_t* b) {
    asm volatile("mma.sync.aligned.m16n8k8.row.col.f32.tf32.tf32.f32 "
        "{%0,%1,%2,%3}, {%4,%5,%6,%7}, {%8,%9}, {%0,%1,%2,%3};"
        : "+f"(d[0]), "+f"(d[1]), "+f"(d[2]), "+f"(d[3])
        : "r"(a[0]), "r"(a[1]), "r"(a[2]), "r"(a[3]), "r"(b[0]), "r"(b[1]));
}
__device__ __forceinline__ void cp_async16(uint32_t dst, const void* src, int src_bytes) {
    asm volatile("cp.async.cg.shared.global [%0], [%1], 16, %2;"
                 :: "r"(dst), "l"(src), "r"(src_bytes));
}
#define CP_COMMIT() asm volatile("cp.async.commit_group;" ::: "memory")
#define CP_WAIT1()  asm volatile("cp.async.wait_group 1;" ::: "memory")

__device__ __forceinline__ float warp_sum(float v) {
    #pragma unroll
    for (int o = 16; o; o >>= 1) v += __shfl_xor_sync(0xffffffffu, v, o);
    return v;
}
__device__ __forceinline__ float warp_max(float v) {
    #pragma unroll
    for (int o = 16; o; o >>= 1) v = fmaxf(v, __shfl_xor_sync(0xffffffffu, v, o));
    return v;
}
__device__ __forceinline__ float gelu_exact(float v) {
    return v * 0.5f * (1.0f + erff(v * 0.7071067811865476f));
}

// ---------------- weight prepass: dst = tf32_round(src) ----------------
__global__ __launch_bounds__(256) void prep_w(const float* __restrict__ src,
                                              float* __restrict__ dst, int n)
{
    int i = (blockIdx.x * 256 + threadIdx.x) * 4;
    if (i + 3 < n) {
        float4 v = *(const float4*)(src + i);
        v.x = round_tf32f(v.x); v.y = round_tf32f(v.y);
        v.z = round_tf32f(v.z); v.w = round_tf32f(v.w);
        *(float4*)(dst + i) = v;
    } else {
        for (int j = i; j < n; j++) dst[j] = round_tf32f(src[j]);
    }
}

// ---------------- tf32 mma.sync GEMM with cp.async 3-stage pipeline ----------------
// C[M,Nn] = A[M,K] @ W[Nn,K]^T + bias (+GELU) (+tf32 round)
// BM=BN=128, BK=32. 256 threads = 8 warps (2 x 4): warp tile 64x32 (4x4 mma tiles).
// SMEM: per stage A(16KB)+B(16KB); 3 stages = 96KB. 16B-chunk XOR swizzle.
#define STAGES 3
#define STAGE_BYTES 32768
#define GEMM_SMEM_BYTES (STAGES * STAGE_BYTES)   // 98304

__global__ void __launch_bounds__(256, 2) gemm_tc(
    const float* __restrict__ A, const float* __restrict__ W,
    const float* __restrict__ bias, float* __restrict__ C,
    int M, int Nn, int K, int do_gelu, int round_out)
{
    extern __shared__ char smc[];
    const uint32_t smb = smem_u32(smc);

    int tid = threadIdx.x;
    int wid = tid >> 5, lane = tid & 31;
    int gid = lane >> 2, tig = lane & 3;
    int wm = (wid & 1) * 64;
    int wn = (wid >> 1) * 32;
    int bm = blockIdx.y * 128, bn = blockIdx.x * 128;

    // copy coords (per thread: 4 x 16B for A, 4 x 16B for B)
    int cprow[4], cpcc[4];
    uint32_t cpsw[4];
    #pragma unroll
    for (int l = 0; l < 4; l++) {
        int id = tid + l * 256;           // 0..1023
        cprow[l] = id >> 3;
        cpcc[l] = id & 7;
        cpsw[l] = ((uint32_t)cprow[l] << 7) | ((uint32_t)((cpcc[l] ^ (cprow[l] & 7)) << 4));
    }

    // fragment LDS offsets
    uint32_t xoff[8];
    #pragma unroll
    for (int c2 = 0; c2 < 8; c2++) xoff[c2] = (uint32_t)((c2 ^ gid) << 4);
    int rowA[4], rowB[4];
    #pragma unroll
    for (int mt = 0; mt < 4; mt++) rowA[mt] = ((wm + mt * 16 + gid) << 7) + tig * 4;
    #pragma unroll
    for (int nt = 0; nt < 4; nt++) rowB[nt] = 16384 + ((wn + nt * 8 + gid) << 7) + tig * 4;

    float acc[4][4][4];
    #pragma unroll
    for (int mt = 0; mt < 4; mt++)
        #pragma unroll
        for (int nt = 0; nt < 4; nt++)
            #pragma unroll
            for (int r = 0; r < 4; r++) acc[mt][nt][r] = 0.f;

    const int NC = K >> 5;

    // stage issuer
    auto issue = [&](int k0, uint32_t sbase) {
        #pragma unroll
        for (int l = 0; l < 4; l++) {
            int gr = bm + cprow[l];
            const float* ga = A + (size_t)(gr < M ? gr : 0) * K + k0 + cpcc[l] * 4;
            cp_async16(sbase + cpsw[l], ga, gr < M ? 16 : 0);
            const float* gw = W + (size_t)(bn + cprow[l]) * K + k0 + cpcc[l] * 4;
            cp_async16(sbase + 16384u + cpsw[l], gw, 16);
        }
    };

    issue(0, smb); CP_COMMIT();
    issue(32, smb + STAGE_BYTES); CP_COMMIT();

    int stage = 0;
    for (int c = 0; c < NC; c++) {
        CP_WAIT1();
        __syncthreads();
        int s2 = stage + 2; if (s2 >= STAGES) s2 -= STAGES;
        if (c + 2 < NC) issue((c + 2) << 5, smb + s2 * STAGE_BYTES);
        CP_COMMIT();

        const char* stp = smc + stage * STAGE_BYTES;
        #pragma unroll
        for (int kk = 0; kk < 4; kk++) {
            uint32_t o0 = xoff[kk * 2], o1 = xoff[kk * 2 + 1];
            uint32_t af[4][4], bf[4][2];
            #pragma unroll
            for (int mt = 0; mt < 4; mt++) {
                af[mt][0] = *(const uint32_t*)(stp + rowA[mt] + o0);
                af[mt][1] = *(const uint32_t*)(stp + rowA[mt] + 1024 + o0);
                af[mt][2] = *(const uint32_t*)(stp + rowA[mt] + o1);
                af[mt][3] = *(const uint32_t*)(stp + rowA[mt] + 1024 + o1);
            }
            #pragma unroll
            for (int nt = 0; nt < 4; nt++) {
                bf[nt][0] = *(const uint32_t*)(stp + rowB[nt] + o0);
                bf[nt][1] = *(const uint32_t*)(stp + rowB[nt] + o1);
            }
            #pragma unroll
            for (int mt = 0; mt < 4; mt++)
                #pragma unroll
                for (int nt = 0; nt < 4; nt++)
                    mma_tf32_16x8x8(acc[mt][nt], af[mt], bf[nt]);
        }
        stage = (stage + 1 == STAGES) ? 0 : stage + 1;
    }

    // epilogue
    #pragma unroll
    for (int mt = 0; mt < 4; mt++) {
        int row0 = bm + wm + mt * 16 + gid;
        #pragma unroll
        for (int half = 0; half < 2; half++) {
            int row = row0 + half * 8;
            if (row >= M) continue;
            float* crow = C + (size_t)row * Nn;
            #pragma unroll
            for (int nt = 0; nt < 4; nt++) {
                int col = bn + wn + nt * 8 + tig * 2;
                float2 o;
                o.x = acc[mt][nt][half * 2 + 0] + bias[col];
                o.y = acc[mt][nt][half * 2 + 1] + bias[col + 1];
                if (do_gelu) { o.x = gelu_exact(o.x); o.y = gelu_exact(o.y); }
                if (round_out) { o.x = round_tf32f(o.x); o.y = round_tf32f(o.y); }
                *(float2*)(crow + col) = o;
            }
        }
    }
}

// ---------------- LayerNorm (+ optional residual adds, + tf32 round) ----------------
__global__ __launch_bounds__(256) void ln_kernel(
    const float* __restrict__ X, const float* __restrict__ gg, const float* __restrict__ bb,
    const float* __restrict__ add1, const float* __restrict__ add2,
    float* __restrict__ out, int Dg, int round_out)
{
    size_t row = blockIdx.x;
    const float* x = X + row * (size_t)Dg;
    float s = 0.f, s2 = 0.f;
    for (int i = threadIdx.x; i < Dg; i += 256) {
        float v = x[i];
        s += v; s2 += v * v;
    }
    __shared__ float sh0[8], sh1[8];
    s = warp_sum(s); s2 = warp_sum(s2);
    int w = threadIdx.x >> 5, lane = threadIdx.x & 31;
    if (lane == 0) { sh0[w] = s; sh1[w] = s2; }
    __syncthreads();
    if (threadIdx.x == 0) {
        float a = 0.f, b2 = 0.f;
        #pragma unroll
        for (int i = 0; i < 8; i++) { a += sh0[i]; b2 += sh1[i]; }
        sh0[0] = a; sh1[0] = b2;
    }
    __syncthreads();
    float invD = 1.0f / (float)Dg;
    float mean = sh0[0] * invD;
    float var  = sh1[0] * invD - mean * mean;
    float rstd = rsqrtf(var + LN_EPS);
    for (int i = threadIdx.x; i < Dg; i += 256) {
        float v = (x[i] - mean) * rstd * gg[i] + bb[i];
        if (add1) v += add1[row * (size_t)Dg + i];
        if (add2) v += add2[row * (size_t)Dg + i];
        if (round_out) v = round_tf32f(v);
        out[row * (size_t)Dg + i] = v;
    }
}

// ---------------- fused attention: one block (512 thr) per (b, h) ----------------
#define HD 96
#define KPAD 97
#define ATTN_THREADS 512
#define ATTN_WARPS 16
#define ATTN_SMEM ((Nseq * KPAD * 2 + ATTN_WARPS * HD + ATTN_WARPS * 204) * 4)
__global__ __launch_bounds__(ATTN_THREADS) void attn_kernel(
    const float* __restrict__ QKV, float* __restrict__ CTX)
{
    extern __shared__ float smf[];
    float* Ks = smf;
    float* Vs = Ks + Nseq * KPAD;
    float* qb = Vs + Nseq * KPAD;
    float* ps = qb + ATTN_WARPS * HD;

    int bh = blockIdx.x;
    int b = bh / NHd, h = bh % NHd;
    int tid = threadIdx.x, lane = tid & 31, w = tid >> 5;

    for (int idx = tid; idx < Nseq * HD; idx += ATTN_THREADS) {
        int r = idx / HD, c = idx - r * HD;
        size_t g = (size_t)(b * Nseq + r) * (3 * Dm) + h * HD + c;
        Ks[r * KPAD + c] = QKV[g + Dm];
        Vs[r * KPAD + c] = QKV[g + 2 * Dm];
    }
    __syncthreads();

    const float scl = rsqrtf((float)HD);
    for (int q = w; q < Nseq; q += ATTN_WARPS) {
        for (int d2 = lane; d2 < HD; d2 += 32)
            qb[w * HD + d2] = QKV[(size_t)(b * Nseq + q) * (3 * Dm) + h * HD + d2];
        __syncwarp();

        float s[7];
        float mx = -1e30f;
        #pragma unroll
        for (int jj = 0; jj < 7; jj++) {
            int j = lane + jj * 32;
            float acc = -1e30f;
            if (j < Nseq) {
                acc = 0.f;
                const float* kr = &Ks[j * KPAD];
                const float* qr = &qb[w * HD];
                #pragma unroll 4
                for (int d2 = 0; d2 < HD; d2++) acc += qr[d2] * kr[d2];
                acc *= scl;
            }
            s[jj] = acc;
            mx = fmaxf(mx, acc);
        }
        mx = warp_max(mx);
        float sum = 0.f;
        #pragma unroll
        for (int jj = 0; jj < 7; jj++) {
            int j = lane + jj * 32;
            if (j < Nseq) {
                float e = expf(s[jj] - mx);
                ps[w * 204 + j] = e;
                sum += e;
            }
        }
        sum = warp_sum(sum);
        float inv = 1.0f / sum;
        __syncwarp();

        for (int d2 = lane; d2 < HD; d2 += 32) {
            float acc = 0.f;
            const float* pw = &ps[w * 204];
            for (int j = 0; j < Nseq; j++) acc += pw[j] * Vs[j * KPAD + d2];
            CTX[(size_t)(b * Nseq + q) * Dm + h * HD + d2] = round_tf32f(acc * inv);
        }
        __syncwarp();
    }
}

// ---------------- fused SO8 gate + LayerNorm ----------------
// y = rot(XP) + base (smem); err -> errOut
// out = LN(y)*g + b + add1 (+ add2)  (optional tf32 round)
__global__ __launch_bounds__(256) void so8ln_kernel(
    const float* __restrict__ XP, const float* __restrict__ base,
    const float* __restrict__ eps, const float* __restrict__ scale_p,
    const float* __restrict__ ln_g, const float* __restrict__ ln_b,
    const float* __restrict__ add1, const float* __restrict__ add2,
    float* __restrict__ out, float* __restrict__ err,
    int Dg, int hd, int round_out)
{
    __shared__ float y[HIDm];
    __shared__ float errsum[8];
    __shared__ float sh0[8], sh1[8];
    size_t row = blockIdx.x;
    int tid = threadIdx.x;
    if (tid < 8) errsum[tid] = 0.f;
    __syncthreads();
    float scale = scale_p[0];
    const float* xp = XP + row * (size_t)Dg;
    const float* bs = base + row * (size_t)Dg;

    float s = 0.f, s2 = 0.f;
    for (int i = tid; i < Dg; i += 256) {
        int head = i / hd;
        int pos = i - head * hd;
        float v;
        if (pos < 8) {
            int pr = pos >> 1;
            float ang = eps[row * 32 + head * 4 + pr] * scale;
            float sn, c;
            sincosf(ang, &sn, &c);
            float e = xp[head * hd + 2 * pr];
            float o = xp[head * hd + 2 * pr + 1];
            float rot, orig;
            if (pos & 1) { rot = e * sn + o * c; orig = o; }
            else         { rot = e * c - o * sn; orig = e; }
            float d = rot - orig;
            atomicAdd(&errsum[head], d * d);
            v = rot;
        } else {
            v = xp[i];
        }
        v += bs[i];
        y[i] = v;
        s += v; s2 += v * v;
    }
    s = warp_sum(s); s2 = warp_sum(s2);
    int w = tid >> 5, lane = tid & 31;
    if (lane == 0) { sh0[w] = s; sh1[w] = s2; }
    __syncthreads();
    if (tid == 0) {
        float a = 0.f, b2 = 0.f;
        #pragma unroll
        for (int i = 0; i < 8; i++) { a += sh0[i]; b2 += sh1[i]; }
        sh0[0] = a; sh1[0] = b2;
        float e = 0.f;
        #pragma unroll
        for (int hh = 0; hh < 8; hh++) e += sqrtf(errsum[hh]);
        err[row] = e * 0.125f;
    }
    __syncthreads();
    float invD = 1.0f / (float)Dg;
    float mean = sh0[0] * invD;
    float var  = sh1[0] * invD - mean * mean;
    float rstd = rsqrtf(var + LN_EPS);
    for (int i = tid; i < Dg; i += 256) {
        float v = (y[i] - mean) * rstd * ln_g[i] + ln_b[i] + add1[row * (size_t)Dg + i];
        if (add2) v += add2[row * (size_t)Dg + i];
        if (round_out) v = round_tf32f(v);
        out[row * (size_t)Dg + i] = v;
    }
}

// ---------------- final concat ----------------
__global__ __launch_bounds__(256) void final_kernel(
    const float* __restrict__ xres, const float* __restrict__ xm,
    const float* __restrict__ e1, const float* __restrict__ e2,
    float* __restrict__ out)
{
    size_t idx = (size_t)blockIdx.x * 256 + threadIdx.x;
    const size_t total = (size_t)BNROWS * Dm;
    if (idx < total) out[idx] = xres[idx] + xm[idx];
    if (idx < BNROWS) out[total + idx] = e1[idx] + e2[idx];
}

// ---------------- launch ----------------
extern "C" void kernel_launch(void* const* d_in, const int* in_sizes, int n_in,
                              void* d_out, int out_size)
{
    const float* x       = (const float*)d_in[0];
    const float* qkv_w   = (const float*)d_in[1];
    const float* qkv_b   = (const float*)d_in[2];
    const float* proj_w  = (const float*)d_in[3];
    const float* proj_b  = (const float*)d_in[4];
    const float* norm1_g = (const float*)d_in[5];
    const float* norm1_b = (const float*)d_in[6];
    const float* norm2_g = (const float*)d_in[7];
    const float* norm2_b = (const float*)d_in[8];
    const float* orth_w_a = (const float*)d_in[9];
    const float* orth_b_a = (const float*)d_in[10];
    const float* scale_a  = (const float*)d_in[11];
    const float* ln_g_a   = (const float*)d_in[12];
    const float* ln_b_a   = (const float*)d_in[13];
    const float* orth_w_m = (const float*)d_in[14];
    const float* orth_b_m = (const float*)d_in[15];
    const float* scale_m  = (const float*)d_in[16];
    const float* ln_g_m   = (const float*)d_in[17];
    const float* ln_b_m   = (const float*)d_in[18];
    const float* fc1_w    = (const float*)d_in[19];
    const float* fc1_b    = (const float*)d_in[20];
    const float* fc2_w    = (const float*)d_in[21];
    const float* fc2_b    = (const float*)d_in[22];
    const float* eps_a    = (const float*)d_in[23];
    const float* eps_m    = (const float*)d_in[24];
    float* out = (float*)d_out;

    float *X1, *QKV, *CTX, *P, *XP, *XRES, *XM, *H1, *H2, *H3, *E1, *E2;
    float *WQKV, *WPROJ, *WOA, *WOM, *WF1, *WF2;
    cudaGetSymbolAddress((void**)&X1,   g_X1);
    cudaGetSymbolAddress((void**)&QKV,  g_QKV);
    cudaGetSymbolAddress((void**)&CTX,  g_CTX);
    cudaGetSymbolAddress((void**)&P,    g_P);
    cudaGetSymbolAddress((void**)&XP,   g_XP);
    cudaGetSymbolAddress((void**)&XRES, g_XRES);
    cudaGetSymbolAddress((void**)&XM,   g_XM);
    cudaGetSymbolAddress((void**)&H1,   g_H1);
    cudaGetSymbolAddress((void**)&H2,   g_H2);
    cudaGetSymbolAddress((void**)&H3,   g_H3);
    cudaGetSymbolAddress((void**)&E1,   g_E1);
    cudaGetSymbolAddress((void**)&E2,   g_E2);
    cudaGetSymbolAddress((void**)&WQKV,  g_WQKV);
    cudaGetSymbolAddress((void**)&WPROJ, g_WPROJ);
    cudaGetSymbolAddress((void**)&WOA,   g_WOA);
    cudaGetSymbolAddress((void**)&WOM,   g_WOM);
    cudaGetSymbolAddress((void**)&WF1,   g_WF1);
    cudaGetSymbolAddress((void**)&WF2,   g_WF2);

    cudaFuncSetAttribute(attn_kernel, cudaFuncAttributeMaxDynamicSharedMemorySize, ATTN_SMEM);
    cudaFuncSetAttribute(gemm_tc, cudaFuncAttributeMaxDynamicSharedMemorySize, GEMM_SMEM_BYTES);

    const int MROWS = BNROWS;
    const int GY = (MROWS + 127) / 128;    // 99
    dim3 blk(256);

    // 0) tf32-round weights
    prep_w<<<(3 * Dm * Dm / 4 + 255) / 256, blk>>>(qkv_w, WQKV, 3 * Dm * Dm);
    prep_w<<<(Dm * Dm / 4 + 255) / 256, blk>>>(proj_w, WPROJ, Dm * Dm);
    prep_w<<<(Dm * Dm / 4 + 255) / 256, blk>>>(orth_w_a, WOA, Dm * Dm);
    prep_w<<<(HIDm * HIDm / 4 + 255) / 256, blk>>>(orth_w_m, WOM, HIDm * HIDm);
    prep_w<<<(HIDm * Dm / 4 + 255) / 256, blk>>>(fc1_w, WF1, HIDm * Dm);
    prep_w<<<(Dm * HIDm / 4 + 255) / 256, blk>>>(fc2_w, WF2, Dm * HIDm);

    // 1) x1 = tf32(LN1(x))
    ln_kernel<<<MROWS, blk>>>(x, norm1_g, norm1_b, nullptr, nullptr, X1, Dm, 1);
    // 2) qkv = x1 @ qkv_w^T + qkv_b
    gemm_tc<<<dim3(3 * Dm / 128, GY), blk, GEMM_SMEM_BYTES>>>(X1, WQKV, qkv_b, QKV, MROWS, 3 * Dm, Dm, 0, 0);
    // 3) attention -> ctx (tf32 rounded)
    attn_kernel<<<Bsz * NHd, ATTN_THREADS, ATTN_SMEM>>>(QKV, CTX);
    // 4) proj -> P (tf32 rounded: feeds orth_a GEMM)
    gemm_tc<<<dim3(Dm / 128, GY), blk, GEMM_SMEM_BYTES>>>(CTX, WPROJ, proj_b, P, MROWS, Dm, Dm, 0, 1);
    // 5) xp = P @ orth_w_a^T + b
    gemm_tc<<<dim3(Dm / 128, GY), blk, GEMM_SMEM_BYTES>>>(P, WOA, orth_b_a, XP, MROWS, Dm, Dm, 0, 0);
    // 6+7) fused so8 + LN: xres = LN(rot(XP)+P)*g+b + P + x  ; err1
    so8ln_kernel<<<MROWS, blk>>>(XP, P, eps_a, scale_a, ln_g_a, ln_b_a, P, x, XRES, E1, Dm, Dm / 8, 0);
    // 8) x2 = tf32(LN2(xres))
    ln_kernel<<<MROWS, blk>>>(XRES, norm2_g, norm2_b, nullptr, nullptr, X1, Dm, 1);
    // 9) h1 = tf32(gelu(x2 @ fc1^T + b))
    gemm_tc<<<dim3(HIDm / 128, GY), blk, GEMM_SMEM_BYTES>>>(X1, WF1, fc1_b, H1, MROWS, HIDm, Dm, 1, 1);
    // 10) h2 = h1 @ orth_w_m^T + b
    gemm_tc<<<dim3(HIDm / 128, GY), blk, GEMM_SMEM_BYTES>>>(H1, WOM, orth_b_m, H2, MROWS, HIDm, HIDm, 0, 0);
    // 11+12) fused so8 + LN: h3 = tf32(LN(rot(H2)+H1)*g+b + H1) ; err2
    so8ln_kernel<<<MROWS, blk>>>(H2, H1, eps_m, scale_m, ln_g_m, ln_b_m, H1, nullptr, H3, E2, HIDm, HIDm / 8, 1);
    // 13) xm = h3 @ fc2^T + b
    gemm_tc<<<dim3(Dm / 128, GY), blk, GEMM_SMEM_BYTES>>>(H3, WF2, fc2_b, XM, MROWS, Dm, HIDm, 0, 0);
    // 14) out
    final_kernel<<<((size_t)MROWS * Dm + 255) / 256, blk>>>(XRES, XM, E1, E2, out);
}

// round 7
// speedup vs baseline: 4.7656x; 1.3990x over previous
#include <cuda_runtime.h>
#include <cuda_fp16.h>
#include <math.h>
#include <stdint.h>

// Problem constants
#define Bsz 64
#define Nseq 197
#define Dm 768
#define NHd 8
#define HIDm 3072
#define BNROWS (Bsz * Nseq)          // 12608
#define LN_EPS 1e-5f

// ---------------- scratch (static device arrays; no allocations) ----------------
__device__ __align__(256) float g_P   [BNROWS * Dm];
__device__ __align__(256) float g_XP  [BNROWS * Dm];
__device__ __align__(256) float g_XRES[BNROWS * Dm];
__device__ __align__(256) float g_H1  [BNROWS * HIDm];
__device__ __align__(256) float g_H2  [BNROWS * HIDm];
__device__ __align__(256) float g_E1  [BNROWS];
// fp16 activation buffers
__device__ __align__(256) __half g_X1h [BNROWS * Dm];
__device__ __align__(256) __half g_QKVh[BNROWS * 3 * Dm];
__device__ __align__(256) __half g_CTXh[BNROWS * Dm];
__device__ __align__(256) __half g_Ph  [BNROWS * Dm];
__device__ __align__(256) __half g_X2h [BNROWS * Dm];
__device__ __align__(256) __half g_H1h [BNROWS * HIDm];
__device__ __align__(256) __half g_H3h [BNROWS * HIDm];
// fp16 weights
__device__ __align__(256) __half g_WQKVh [3 * Dm * Dm];
__device__ __align__(256) __half g_WPROJh[Dm * Dm];
__device__ __align__(256) __half g_WOAh  [Dm * Dm];
__device__ __align__(256) __half g_WOMh  [HIDm * HIDm];
__device__ __align__(256) __half g_WF1h  [HIDm * Dm];
__device__ __align__(256) __half g_WF2h  [Dm * HIDm];

// ---------------- helpers ----------------
__device__ __forceinline__ uint32_t smem_u32(const void* p) {
    uint32_t a;
    asm("{ .reg .u64 t; cvta.to.shared.u64 t, %1; cvt.u32.u64 %0, t; }" : "=r"(a) : "l"(p));
    return a;
}
__device__ __forceinline__ void ldsm_x4(uint32_t* r, uint32_t addr) {
    asm volatile("ldmatrix.sync.aligned.m8n8.x4.shared.b16 {%0,%1,%2,%3}, [%4];"
        : "=r"(r[0]), "=r"(r[1]), "=r"(r[2]), "=r"(r[3]) : "r"(addr));
}
__device__ __forceinline__ void mma_f16(float* d, const uint32_t* a, const uint32_t* b) {
    asm volatile("mma.sync.aligned.m16n8k16.row.col.f32.f16.f16.f32 "
        "{%0,%1,%2,%3}, {%4,%5,%6,%7}, {%8,%9}, {%0,%1,%2,%3};"
        : "+f"(d[0]), "+f"(d[1]), "+f"(d[2]), "+f"(d[3])
        : "r"(a[0]), "r"(a[1]), "r"(a[2]), "r"(a[3]), "r"(b[0]), "r"(b[1]));
}
__device__ __forceinline__ void cp_async16(uint32_t dst, const void* src, int src_bytes) {
    asm volatile("cp.async.cg.shared.global [%0], [%1], 16, %2;"
                 :: "r"(dst), "l"(src), "r"(src_bytes));
}
#define CP_COMMIT() asm volatile("cp.async.commit_group;" ::: "memory")
#define CP_WAIT1()  asm volatile("cp.async.wait_group 1;" ::: "memory")

__device__ __forceinline__ float warp_sum(float v) {
    #pragma unroll
    for (int o = 16; o; o >>= 1) v += __shfl_xor_sync(0xffffffffu, v, o);
    return v;
}
__device__ __forceinline__ float gelu_exact(float v) {
    return v * 0.5f * (1.0f + erff(v * 0.7071067811865476f));
}

// ---------------- weight prepass: dst = fp16(src) ----------------
__global__ __launch_bounds__(256) void prep_w16(const float* __restrict__ src,
                                                __half* __restrict__ dst, int n)
{
    int i = (blockIdx.x * 256 + threadIdx.x) * 4;
    if (i + 3 < n) {
        float4 v = *(const float4*)(src + i);
        __half2 h0 = __floats2half2_rn(v.x, v.y);
        __half2 h1 = __floats2half2_rn(v.z, v.w);
        *(__half2*)(dst + i) = h0;
        *(__half2*)(dst + i + 2) = h1;
    } else {
        for (int j = i; j < n; j++) dst[j] = __float2half(src[j]);
    }
}

// ---------------- fp16 mma.sync GEMM (ldmatrix + cp.async 3-stage) ----------------
// C[M,Nn] = A[M,K] @ W[Nn,K]^T + bias (+GELU) (+add residual)
// BM=BN=128, BK=64. 256 threads = 8 warps (2 x 4): warp tile 64x32.
// Stage: A 16KB + B 16KB = 32KB; 3 stages = 96KB. 16B-chunk XOR swizzle, 128B rows.
#define STAGES 3
#define STAGE_BYTES 32768
#define GEMM_SMEM_BYTES (STAGES * STAGE_BYTES)   // 98304

__global__ void __launch_bounds__(256, 2) gemm_tc(
    const __half* __restrict__ A, const __half* __restrict__ W,
    const float* __restrict__ bias,
    float* __restrict__ C32, __half* __restrict__ C16,
    const float* __restrict__ add,
    int M, int Nn, int K, int do_gelu)
{
    extern __shared__ char smc[];
    const uint32_t smb = smem_u32(smc);

    int tid = threadIdx.x;
    int wid = tid >> 5, lane = tid & 31;
    int gid = lane >> 2, tig = lane & 3;
    int lane16 = lane & 15, khalf = lane >> 4;
    int wm = (wid & 1) * 64;
    int wn = (wid >> 1) * 32;
    int bm = blockIdx.y * 128, bn = blockIdx.x * 128;

    // copy coords: per thread 4 A-chunks + 4 B-chunks of 16B
    int cprow[4], cpc[4];
    uint32_t cpsw[4];
    #pragma unroll
    for (int l = 0; l < 4; l++) {
        int f = tid + l * 256;            // 0..1023
        cprow[l] = f >> 3;
        cpc[l] = f & 7;
        cpsw[l] = ((uint32_t)cprow[l] << 7) | ((uint32_t)((cpc[l] ^ (cprow[l] & 7)) << 4));
    }

    // ldmatrix lane bases
    uint32_t rx = (uint32_t)(lane16 & 7);
    uint32_t aoff[4], boff[2];
    #pragma unroll
    for (int mt = 0; mt < 4; mt++) aoff[mt] = (uint32_t)((wm + mt * 16 + lane16) << 7);
    #pragma unroll
    for (int p = 0; p < 2; p++) boff[p] = 16384u + (uint32_t)((wn + p * 16 + lane16) << 7);

    float acc[4][4][4];
    #pragma unroll
    for (int mt = 0; mt < 4; mt++)
        #pragma unroll
        for (int nt = 0; nt < 4; nt++)
            #pragma unroll
            for (int r = 0; r < 4; r++) acc[mt][nt][r] = 0.f;

    const int NC = K >> 6;

    auto issue = [&](int k0, uint32_t sbase) {
        #pragma unroll
        for (int l = 0; l < 4; l++) {
            int gr = bm + cprow[l];
            const __half* ga = A + (size_t)(gr < M ? gr : 0) * K + k0 + cpc[l] * 8;
            cp_async16(sbase + cpsw[l], ga, gr < M ? 16 : 0);
            const __half* gw = W + (size_t)(bn + cprow[l]) * K + k0 + cpc[l] * 8;
            cp_async16(sbase + 16384u + cpsw[l], gw, 16);
        }
    };

    issue(0, smb); CP_COMMIT();
    issue(64, smb + STAGE_BYTES); CP_COMMIT();

    int stage = 0;
    for (int c = 0; c < NC; c++) {
        CP_WAIT1();
        __syncthreads();
        int s2 = stage + 2; if (s2 >= STAGES) s2 -= STAGES;
        if (c + 2 < NC) issue((c + 2) << 6, smb + s2 * STAGE_BYTES);
        CP_COMMIT();

        const uint32_t stb = smb + stage * STAGE_BYTES;
        #pragma unroll
        for (int kk = 0; kk < 4; kk++) {
            uint32_t kb = (uint32_t)(((((kk << 1) | khalf)) ^ rx) << 4);
            uint32_t af[4][4], bf[2][4];
            #pragma unroll
            for (int mt = 0; mt < 4; mt++) ldsm_x4(af[mt], stb + aoff[mt] + kb);
            #pragma unroll
            for (int p = 0; p < 2; p++) ldsm_x4(bf[p], stb + boff[p] + kb);
            #pragma unroll
            for (int mt = 0; mt < 4; mt++) {
                #pragma unroll
                for (int nt = 0; nt < 4; nt++) {
                    int p = nt >> 1, s = nt & 1;
                    uint32_t bb[2] = { bf[p][s], bf[p][2 + s] };
                    mma_f16(acc[mt][nt], af[mt], bb);
                }
            }
        }
        stage = (stage + 1 == STAGES) ? 0 : stage + 1;
    }

    // epilogue
    #pragma unroll
    for (int mt = 0; mt < 4; mt++) {
        int row0 = bm + wm + mt * 16 + gid;
        #pragma unroll
        for (int half_ = 0; half_ < 2; half_++) {
            int row = row0 + half_ * 8;
            if (row >= M) continue;
            #pragma unroll
            for (int nt = 0; nt < 4; nt++) {
                int col = bn + wn + nt * 8 + tig * 2;
                float2 o;
                o.x = acc[mt][nt][half_ * 2 + 0] + bias[col];
                o.y = acc[mt][nt][half_ * 2 + 1] + bias[col + 1];
                if (do_gelu) { o.x = gelu_exact(o.x); o.y = gelu_exact(o.y); }
                if (add) {
                    const float2 a2 = *(const float2*)(add + (size_t)row * Nn + col);
                    o.x += a2.x; o.y += a2.y;
                }
                if (C32) *(float2*)(C32 + (size_t)row * Nn + col) = o;
                if (C16) *(__half2*)(C16 + (size_t)row * Nn + col) = __floats2half2_rn(o.x, o.y);
            }
        }
    }
}

// ---------------- LayerNorm -> fp16 out ----------------
__global__ __launch_bounds__(256) void ln16_kernel(
    const float* __restrict__ X, const float* __restrict__ gg, const float* __restrict__ bb,
    __half* __restrict__ out, int Dg)
{
    size_t row = blockIdx.x;
    const float* x = X + row * (size_t)Dg;
    float s = 0.f, s2 = 0.f;
    for (int i = threadIdx.x; i < Dg; i += 256) {
        float v = x[i];
        s += v; s2 += v * v;
    }
    __shared__ float sh0[8], sh1[8];
    s = warp_sum(s); s2 = warp_sum(s2);
    int w = threadIdx.x >> 5, lane = threadIdx.x & 31;
    if (lane == 0) { sh0[w] = s; sh1[w] = s2; }
    __syncthreads();
    float ts = 0.f, ts2 = 0.f;
    #pragma unroll
    for (int i = 0; i < 8; i++) { ts += sh0[i]; ts2 += sh1[i]; }
    float invD = 1.0f / (float)Dg;
    float mean = ts * invD;
    float var  = ts2 * invD - mean * mean;
    float rstd = rsqrtf(var + LN_EPS);
    for (int i = threadIdx.x; i < Dg; i += 256)
        out[row * (size_t)Dg + i] = __float2half((x[i] - mean) * rstd * gg[i] + bb[i]);
}

// ---------------- fused attention (fp16 in/out): one block (512 thr) per (b, h) ----
#define HD 96
#define KPAD 97
#define ATTN_THREADS 512
#define ATTN_WARPS 16
#define ATTN_SMEM ((Nseq * KPAD * 2 + ATTN_WARPS * HD + ATTN_WARPS * 204) * 4)
__global__ __launch_bounds__(ATTN_THREADS) void attn_kernel(
    const __half* __restrict__ QKV, __half* __restrict__ CTX)
{
    extern __shared__ float smf[];
    float* Ks = smf;
    float* Vs = Ks + Nseq * KPAD;
    float* qb = Vs + Nseq * KPAD;
    float* ps = qb + ATTN_WARPS * HD;

    int bh = blockIdx.x;
    int b = bh / NHd, h = bh % NHd;
    int tid = threadIdx.x, lane = tid & 31, w = tid >> 5;

    for (int idx = tid; idx < Nseq * HD; idx += ATTN_THREADS) {
        int r = idx / HD, c = idx - r * HD;
        size_t g = (size_t)(b * Nseq + r) * (3 * Dm) + h * HD + c;
        Ks[r * KPAD + c] = __half2float(QKV[g + Dm]);
        Vs[r * KPAD + c] = __half2float(QKV[g + 2 * Dm]);
    }
    __syncthreads();

    const float scl = rsqrtf((float)HD);
    for (int q = w; q < Nseq; q += ATTN_WARPS) {
        for (int d2 = lane; d2 < HD; d2 += 32)
            qb[w * HD + d2] = __half2float(QKV[(size_t)(b * Nseq + q) * (3 * Dm) + h * HD + d2]);
        __syncwarp();

        float s[7];
        float mx = -1e30f;
        #pragma unroll
        for (int jj = 0; jj < 7; jj++) {
            int j = lane + jj * 32;
            float acc = -1e30f;
            if (j < Nseq) {
                acc = 0.f;
                const float* kr = &Ks[j * KPAD];
                const float* qr = &qb[w * HD];
                #pragma unroll 4
                for (int d2 = 0; d2 < HD; d2++) acc += qr[d2] * kr[d2];
                acc *= scl;
            }
            s[jj] = acc;
            mx = fmaxf(mx, acc);
        }
        #pragma unroll
        for (int o = 16; o; o >>= 1) mx = fmaxf(mx, __shfl_xor_sync(0xffffffffu, mx, o));
        float sum = 0.f;
        #pragma unroll
        for (int jj = 0; jj < 7; jj++) {
            int j = lane + jj * 32;
            if (j < Nseq) {
                float e = expf(s[jj] - mx);
                ps[w * 204 + j] = e;
                sum += e;
            }
        }
        sum = warp_sum(sum);
        float inv = 1.0f / sum;
        __syncwarp();

        for (int d2 = lane; d2 < HD; d2 += 32) {
            float acc = 0.f;
            const float* pw = &ps[w * 204];
            for (int j = 0; j < Nseq; j++) acc += pw[j] * Vs[j * KPAD + d2];
            CTX[(size_t)(b * Nseq + q) * Dm + h * HD + d2] = __float2half(acc * inv);
        }
        __syncwarp();
    }
}

// ---------------- adapter A: so8 + LN_a + residual + fused LN2 -> fp16 ----------------
// y = rot(XP)+P ; err1
// xres = LN_a(y)*g1+b1 + P + x          (fp32 out, residual for fc2)
// x2h  = fp16(LN2(xres)*g2+b2)          (fp16 out, feeds fc1)
__global__ __launch_bounds__(256) void so8ln_a_kernel(
    const float* __restrict__ XP, const float* __restrict__ P, const float* __restrict__ xin,
    const float* __restrict__ eps, const float* __restrict__ scale_p,
    const float* __restrict__ g1, const float* __restrict__ b1,
    const float* __restrict__ g2, const float* __restrict__ b2,
    float* __restrict__ XRES, __half* __restrict__ X2h, float* __restrict__ err)
{
    __shared__ float y[Dm];
    __shared__ float errsum[8];
    __shared__ float sh0[8], sh1[8];
    size_t row = blockIdx.x;
    int tid = threadIdx.x;
    const int hd = Dm / 8;
    if (tid < 8) errsum[tid] = 0.f;
    __syncthreads();
    float scale = scale_p[0];
    const float* xp = XP + row * (size_t)Dm;
    const float* bs = P + row * (size_t)Dm;

    float s = 0.f, s2 = 0.f;
    for (int i = tid; i < Dm; i += 256) {
        int head = i / hd;
        int pos = i - head * hd;
        float v;
        if (pos < 8) {
            int pr = pos >> 1;
            float ang = eps[row * 32 + head * 4 + pr] * scale;
            float sn, c;
            sincosf(ang, &sn, &c);
            float e = xp[head * hd + 2 * pr];
            float o = xp[head * hd + 2 * pr + 1];
            float rot, orig;
            if (pos & 1) { rot = e * sn + o * c; orig = o; }
            else         { rot = e * c - o * sn; orig = e; }
            float d = rot - orig;
            atomicAdd(&errsum[head], d * d);
            v = rot;
        } else v = xp[i];
        v += bs[i];
        y[i] = v;
        s += v; s2 += v * v;
    }
    s = warp_sum(s); s2 = warp_sum(s2);
    int w = tid >> 5, lane = tid & 31;
    if (lane == 0) { sh0[w] = s; sh1[w] = s2; }
    __syncthreads();
    float ts = 0.f, ts2 = 0.f;
    #pragma unroll
    for (int i = 0; i < 8; i++) { ts += sh0[i]; ts2 += sh1[i]; }
    if (tid == 0) {
        float e = 0.f;
        #pragma unroll
        for (int hh = 0; hh < 8; hh++) e += sqrtf(errsum[hh]);
        err[row] = e * 0.125f;
    }
    const float invD = 1.0f / (float)Dm;
    float mean = ts * invD;
    float rstd = rsqrtf(ts2 * invD - mean * mean + LN_EPS);
    __syncthreads();

    // pass 2: xres
    s = 0.f; s2 = 0.f;
    for (int i = tid; i < Dm; i += 256) {
        float v = (y[i] - mean) * rstd * g1[i] + b1[i] + bs[i] + xin[row * (size_t)Dm + i];
        XRES[row * (size_t)Dm + i] = v;
        y[i] = v;
        s += v; s2 += v * v;
    }
    s = warp_sum(s); s2 = warp_sum(s2);
    if (lane == 0) { sh0[w] = s; sh1[w] = s2; }
    __syncthreads();
    ts = 0.f; ts2 = 0.f;
    #pragma unroll
    for (int i = 0; i < 8; i++) { ts += sh0[i]; ts2 += sh1[i]; }
    float mean2 = ts * invD;
    float rstd2 = rsqrtf(ts2 * invD - mean2 * mean2 + LN_EPS);
    for (int i = tid; i < Dm; i += 256)
        X2h[row * (size_t)Dm + i] = __float2half((y[i] - mean2) * rstd2 * g2[i] + b2[i]);
}

// ---------------- adapter M: so8 + LN_m + residual -> fp16 ; err tail ----------------
// y = rot(H2)+H1 ; err2 ; out_tail[row] = e1[row]+err2
// h3h = fp16(LN_m(y)*g+b + H1)
__global__ __launch_bounds__(256) void so8ln_m_kernel(
    const float* __restrict__ H2, const float* __restrict__ H1,
    const float* __restrict__ eps, const float* __restrict__ scale_p,
    const float* __restrict__ gg, const float* __restrict__ bb,
    const float* __restrict__ e1, float* __restrict__ out_tail,
    __half* __restrict__ H3h)
{
    __shared__ float y[HIDm];
    __shared__ float errsum[8];
    __shared__ float sh0[8], sh1[8];
    size_t row = blockIdx.x;
    int tid = threadIdx.x;
    const int hd = HIDm / 8;
    if (tid < 8) errsum[tid] = 0.f;
    __syncthreads();
    float scale = scale_p[0];
    const float* xp = H2 + row * (size_t)HIDm;
    const float* bs = H1 + row * (size_t)HIDm;

    float s = 0.f, s2 = 0.f;
    for (int i = tid; i < HIDm; i += 256) {
        int head = i / hd;
        int pos = i - head * hd;
        float v;
        if (pos < 8) {
            int pr = pos >> 1;
            float ang = eps[row * 32 + head * 4 + pr] * scale;
            float sn, c;
            sincosf(ang, &sn, &c);
            float e = xp[head * hd + 2 * pr];
            float o = xp[head * hd + 2 * pr + 1];
            float rot, orig;
            if (pos & 1) { rot = e * sn + o * c; orig = o; }
            else         { rot = e * c - o * sn; orig = e; }
            float d = rot - orig;
            atomicAdd(&errsum[head], d * d);
            v = rot;
        } else v = xp[i];
        v += bs[i];
        y[i] = v;
        s += v; s2 += v * v;
    }
    s = warp_sum(s); s2 = warp_sum(s2);
    int w = tid >> 5, lane = tid & 31;
    if (lane == 0) { sh0[w] = s; sh1[w] = s2; }
    __syncthreads();
    float ts = 0.f, ts2 = 0.f;
    #pragma unroll
    for (int i = 0; i < 8; i++) { ts += sh0[i]; ts2 += sh1[i]; }
    if (tid == 0) {
        float e = 0.f;
        #pragma unroll
        for (int hh = 0; hh < 8; hh++) e += sqrtf(errsum[hh]);
        out_tail[row] = e * 0.125f + e1[row];
    }
    const float invD = 1.0f / (float)HIDm;
    float mean = ts * invD;
    float rstd = rsqrtf(ts2 * invD - mean * mean + LN_EPS);
    for (int i = tid; i < HIDm; i += 256)
        H3h[row * (size_t)HIDm + i] =
            __float2half((y[i] - mean) * rstd * gg[i] + bb[i] + bs[i]);
}

// ---------------- launch ----------------
extern "C" void kernel_launch(void* const* d_in, const int* in_sizes, int n_in,
                              void* d_out, int out_size)
{
    const float* x       = (const float*)d_in[0];
    const float* qkv_w   = (const float*)d_in[1];
    const float* qkv_b   = (const float*)d_in[2];
    const float* proj_w  = (const float*)d_in[3];
    const float* proj_b  = (const float*)d_in[4];
    const float* norm1_g = (const float*)d_in[5];
    const float* norm1_b = (const float*)d_in[6];
    const float* norm2_g = (const float*)d_in[7];
    const float* norm2_b = (const float*)d_in[8];
    const float* orth_w_a = (const float*)d_in[9];
    const float* orth_b_a = (const float*)d_in[10];
    const float* scale_a  = (const float*)d_in[11];
    const float* ln_g_a   = (const float*)d_in[12];
    const float* ln_b_a   = (const float*)d_in[13];
    const float* orth_w_m = (const float*)d_in[14];
    const float* orth_b_m = (const float*)d_in[15];
    const float* scale_m  = (const float*)d_in[16];
    const float* ln_g_m   = (const float*)d_in[17];
    const float* ln_b_m   = (const float*)d_in[18];
    const float* fc1_w    = (const float*)d_in[19];
    const float* fc1_b    = (const float*)d_in[20];
    const float* fc2_w    = (const float*)d_in[21];
    const float* fc2_b    = (const float*)d_in[22];
    const float* eps_a    = (const float*)d_in[23];
    const float* eps_m    = (const float*)d_in[24];
    float* out = (float*)d_out;

    float *P, *XP, *XRES, *H1, *H2, *E1;
    __half *X1h, *QKVh, *CTXh, *Ph, *X2h, *H1h, *H3h;
    __half *WQKVh, *WPROJh, *WOAh, *WOMh, *WF1h, *WF2h;
    cudaGetSymbolAddress((void**)&P,    g_P);
    cudaGetSymbolAddress((void**)&XP,   g_XP);
    cudaGetSymbolAddress((void**)&XRES, g_XRES);
    cudaGetSymbolAddress((void**)&H1,   g_H1);
    cudaGetSymbolAddress((void**)&H2,   g_H2);
    cudaGetSymbolAddress((void**)&E1,   g_E1);
    cudaGetSymbolAddress((void**)&X1h,  g_X1h);
    cudaGetSymbolAddress((void**)&QKVh, g_QKVh);
    cudaGetSymbolAddress((void**)&CTXh, g_CTXh);
    cudaGetSymbolAddress((void**)&Ph,   g_Ph);
    cudaGetSymbolAddress((void**)&X2h,  g_X2h);
    cudaGetSymbolAddress((void**)&H1h,  g_H1h);
    cudaGetSymbolAddress((void**)&H3h,  g_H3h);
    cudaGetSymbolAddress((void**)&WQKVh,  g_WQKVh);
    cudaGetSymbolAddress((void**)&WPROJh, g_WPROJh);
    cudaGetSymbolAddress((void**)&WOAh,   g_WOAh);
    cudaGetSymbolAddress((void**)&WOMh,   g_WOMh);
    cudaGetSymbolAddress((void**)&WF1h,   g_WF1h);
    cudaGetSymbolAddress((void**)&WF2h,   g_WF2h);

    cudaFuncSetAttribute(attn_kernel, cudaFuncAttributeMaxDynamicSharedMemorySize, ATTN_SMEM);
    cudaFuncSetAttribute(gemm_tc, cudaFuncAttributeMaxDynamicSharedMemorySize, GEMM_SMEM_BYTES);

    const int MROWS = BNROWS;
    const int GY = (MROWS + 127) / 128;    // 99
    dim3 blk(256);

    // 0) fp16 weights
    prep_w16<<<(3 * Dm * Dm / 4 + 255) / 256, blk>>>(qkv_w, WQKVh, 3 * Dm * Dm);
    prep_w16<<<(Dm * Dm / 4 + 255) / 256, blk>>>(proj_w, WPROJh, Dm * Dm);
    prep_w16<<<(Dm * Dm / 4 + 255) / 256, blk>>>(orth_w_a, WOAh, Dm * Dm);
    prep_w16<<<(HIDm * HIDm / 4 + 255) / 256, blk>>>(orth_w_m, WOMh, HIDm * HIDm);
    prep_w16<<<(HIDm * Dm / 4 + 255) / 256, blk>>>(fc1_w, WF1h, HIDm * Dm);
    prep_w16<<<(Dm * HIDm / 4 + 255) / 256, blk>>>(fc2_w, WF2h, Dm * HIDm);

    // 1) x1h = fp16(LN1(x))
    ln16_kernel<<<MROWS, blk>>>(x, norm1_g, norm1_b, X1h, Dm);
    // 2) qkvh = x1 @ qkv_w^T + qkv_b (fp16 only)
    gemm_tc<<<dim3(3 * Dm / 128, GY), blk, GEMM_SMEM_BYTES>>>(
        X1h, WQKVh, qkv_b, nullptr, QKVh, nullptr, MROWS, 3 * Dm, Dm, 0);
    // 3) attention -> ctxh (fp16)
    attn_kernel<<<Bsz * NHd, ATTN_THREADS, ATTN_SMEM>>>(QKVh, CTXh);
    // 4) proj -> P (fp32) + Ph (fp16)
    gemm_tc<<<dim3(Dm / 128, GY), blk, GEMM_SMEM_BYTES>>>(
        CTXh, WPROJh, proj_b, P, Ph, nullptr, MROWS, Dm, Dm, 0);
    // 5) xp = P @ orth_w_a^T + b (fp32)
    gemm_tc<<<dim3(Dm / 128, GY), blk, GEMM_SMEM_BYTES>>>(
        Ph, WOAh, orth_b_a, XP, nullptr, nullptr, MROWS, Dm, Dm, 0);
    // 6) adapter A fused: xres (fp32) + x2h (fp16) + err1
    so8ln_a_kernel<<<MROWS, blk>>>(XP, P, x, eps_a, scale_a,
                                   ln_g_a, ln_b_a, norm2_g, norm2_b, XRES, X2h, E1);
    // 7) h1 = gelu(x2 @ fc1^T + b) -> H1 (fp32) + H1h (fp16)
    gemm_tc<<<dim3(HIDm / 128, GY), blk, GEMM_SMEM_BYTES>>>(
        X2h, WF1h, fc1_b, H1, H1h, nullptr, MROWS, HIDm, Dm, 1);
    // 8) h2 = h1 @ orth_w_m^T + b (fp32)
    gemm_tc<<<dim3(HIDm / 128, GY), blk, GEMM_SMEM_BYTES>>>(
        H1h, WOMh, orth_b_m, H2, nullptr, nullptr, MROWS, HIDm, HIDm, 0);
    // 9) adapter M fused: h3h (fp16) + out tail (e1+e2)
    so8ln_m_kernel<<<MROWS, blk>>>(H2, H1, eps_m, scale_m, ln_g_m, ln_b_m,
                                   E1, out + (size_t)MROWS * Dm, H3h);
    // 10) out = h3 @ fc2^T + b + xres  (writes d_out directly)
    gemm_tc<<<dim3(Dm / 128, GY), blk, GEMM_SMEM_BYTES>>>(
        H3h, WF2h, fc2_b, out, nullptr, XRES, MROWS, Dm, HIDm, 0);
}

// round 8
// speedup vs baseline: 4.8709x; 1.0221x over previous
#include <cuda_runtime.h>
#include <cuda_fp16.h>
#include <math.h>
#include <stdint.h>

// Problem constants
#define Bsz 64
#define Nseq 197
#define Dm 768
#define NHd 8
#define HIDm 3072
#define BNROWS (Bsz * Nseq)          // 12608
#define LN_EPS 1e-5f

// ---------------- scratch (static device arrays; no allocations) ----------------
__device__ __align__(256) float g_P   [BNROWS * Dm];
__device__ __align__(256) float g_XP  [BNROWS * Dm];
__device__ __align__(256) float g_XRES[BNROWS * Dm];
__device__ __align__(256) float g_H2  [BNROWS * HIDm];
__device__ __align__(256) float g_E1  [BNROWS];
// fp16 activation buffers
__device__ __align__(256) __half g_X1h [BNROWS * Dm];
__device__ __align__(256) __half g_QKVh[BNROWS * 3 * Dm];
__device__ __align__(256) __half g_CTXh[BNROWS * Dm];
__device__ __align__(256) __half g_Ph  [BNROWS * Dm];
__device__ __align__(256) __half g_X2h [BNROWS * Dm];
__device__ __align__(256) __half g_H1h [BNROWS * HIDm];
__device__ __align__(256) __half g_H3h [BNROWS * HIDm];
// fp16 weights
__device__ __align__(256) __half g_WQKVh [3 * Dm * Dm];
__device__ __align__(256) __half g_WPROJh[Dm * Dm];
__device__ __align__(256) __half g_WOAh  [Dm * Dm];
__device__ __align__(256) __half g_WOMh  [HIDm * HIDm];
__device__ __align__(256) __half g_WF1h  [HIDm * Dm];
__device__ __align__(256) __half g_WF2h  [Dm * HIDm];

// ---------------- helpers ----------------
__device__ __forceinline__ uint32_t smem_u32(const void* p) {
    uint32_t a;
    asm("{ .reg .u64 t; cvta.to.shared.u64 t, %1; cvt.u32.u64 %0, t; }" : "=r"(a) : "l"(p));
    return a;
}
__device__ __forceinline__ void ldsm_x4(uint32_t* r, uint32_t addr) {
    asm volatile("ldmatrix.sync.aligned.m8n8.x4.shared.b16 {%0,%1,%2,%3}, [%4];"
        : "=r"(r[0]), "=r"(r[1]), "=r"(r[2]), "=r"(r[3]) : "r"(addr));
}
__device__ __forceinline__ void mma_f16(float* d, const uint32_t* a, const uint32_t* b) {
    asm volatile("mma.sync.aligned.m16n8k16.row.col.f32.f16.f16.f32 "
        "{%0,%1,%2,%3}, {%4,%5,%6,%7}, {%8,%9}, {%0,%1,%2,%3};"
        : "+f"(d[0]), "+f"(d[1]), "+f"(d[2]), "+f"(d[3])
        : "r"(a[0]), "r"(a[1]), "r"(a[2]), "r"(a[3]), "r"(b[0]), "r"(b[1]));
}
__device__ __forceinline__ void cp_async16(uint32_t dst, const void* src, int src_bytes) {
    asm volatile("cp.async.cg.shared.global [%0], [%1], 16, %2;"
                 :: "r"(dst), "l"(src), "r"(src_bytes));
}
#define CP_COMMIT() asm volatile("cp.async.commit_group;" ::: "memory")
#define CP_WAIT1()  asm volatile("cp.async.wait_group 1;" ::: "memory")

// packed f32x2
__device__ __forceinline__ unsigned long long dup2(float a) {
    unsigned long long r;
    asm("mov.b64 %0, {%1, %1};" : "=l"(r) : "f"(a));
    return r;
}
__device__ __forceinline__ unsigned long long ffma2(unsigned long long a, unsigned long long b,
                                                    unsigned long long c) {
    unsigned long long d;
    asm("fma.rn.f32x2 %0, %1, %2, %3;" : "=l"(d) : "l"(a), "l"(b), "l"(c));
    return d;
}
__device__ __forceinline__ void unpack2(unsigned long long v, float& lo, float& hi) {
    asm("mov.b64 {%0, %1}, %2;" : "=f"(lo), "=f"(hi) : "l"(v));
}

__device__ __forceinline__ float warp_sum(float v) {
    #pragma unroll
    for (int o = 16; o; o >>= 1) v += __shfl_xor_sync(0xffffffffu, v, o);
    return v;
}
__device__ __forceinline__ float gelu_exact(float v) {
    return v * 0.5f * (1.0f + erff(v * 0.7071067811865476f));
}

// ---------------- merged weight prepass: all 6 weights fp32 -> fp16 ----------------
#define SZ_QKV (3 * Dm * Dm)
#define SZ_PRJ (Dm * Dm)
#define SZ_OM  (HIDm * HIDm)
#define SZ_F1  (HIDm * Dm)
#define CUM0 SZ_QKV
#define CUM1 (CUM0 + SZ_PRJ)
#define CUM2 (CUM1 + SZ_PRJ)
#define CUM3 (CUM2 + SZ_OM)
#define CUM4 (CUM3 + SZ_F1)
#define CUM5 (CUM4 + SZ_F1)
__global__ __launch_bounds__(256) void prep_all(
    const float* __restrict__ qkv_w, const float* __restrict__ proj_w,
    const float* __restrict__ orth_a, const float* __restrict__ orth_m,
    const float* __restrict__ fc1_w, const float* __restrict__ fc2_w)
{
    __half *WQKVh, *WPROJh, *WOAh, *WOMh, *WF1h, *WF2h;
    WQKVh = g_WQKVh; WPROJh = g_WPROJh; WOAh = g_WOAh;
    WOMh = g_WOMh; WF1h = g_WF1h; WF2h = g_WF2h;
    int i = ((int)blockIdx.x * 256 + (int)threadIdx.x) * 4;
    if (i >= CUM5) return;
    const float* src; __half* dst; int off;
    if (i < CUM0)      { src = qkv_w;  dst = WQKVh;  off = i; }
    else if (i < CUM1) { src = proj_w; dst = WPROJh; off = i - CUM0; }
    else if (i < CUM2) { src = orth_a; dst = WOAh;   off = i - CUM1; }
    else if (i < CUM3) { src = orth_m; dst = WOMh;   off = i - CUM2; }
    else if (i < CUM4) { src = fc1_w;  dst = WF1h;   off = i - CUM3; }
    else               { src = fc2_w;  dst = WF2h;   off = i - CUM4; }
    float4 v = *(const float4*)(src + off);
    *(__half2*)(dst + off)     = __floats2half2_rn(v.x, v.y);
    *(__half2*)(dst + off + 2) = __floats2half2_rn(v.z, v.w);
}

// ---------------- fp16 mma.sync GEMM (ldmatrix + cp.async 3-stage) ----------------
#define STAGES 3
#define STAGE_BYTES 32768
#define GEMM_SMEM_BYTES (STAGES * STAGE_BYTES)   // 98304

__global__ void __launch_bounds__(256, 2) gemm_tc(
    const __half* __restrict__ A, const __half* __restrict__ W,
    const float* __restrict__ bias,
    float* __restrict__ C32, __half* __restrict__ C16,
    const float* __restrict__ add,
    int M, int Nn, int K, int do_gelu)
{
    extern __shared__ char smc[];
    const uint32_t smb = smem_u32(smc);

    int tid = threadIdx.x;
    int wid = tid >> 5, lane = tid & 31;
    int gid = lane >> 2, tig = lane & 3;
    int lane16 = lane & 15, khalf = lane >> 4;
    int wm = (wid & 1) * 64;
    int wn = (wid >> 1) * 32;
    int bm = blockIdx.y * 128, bn = blockIdx.x * 128;

    int cprow[4], cpc[4];
    uint32_t cpsw[4];
    #pragma unroll
    for (int l = 0; l < 4; l++) {
        int f = tid + l * 256;
        cprow[l] = f >> 3;
        cpc[l] = f & 7;
        cpsw[l] = ((uint32_t)cprow[l] << 7) | ((uint32_t)((cpc[l] ^ (cprow[l] & 7)) << 4));
    }

    uint32_t rx = (uint32_t)(lane16 & 7);
    uint32_t aoff[4], boff[2];
    #pragma unroll
    for (int mt = 0; mt < 4; mt++) aoff[mt] = (uint32_t)((wm + mt * 16 + lane16) << 7);
    #pragma unroll
    for (int p = 0; p < 2; p++) boff[p] = 16384u + (uint32_t)((wn + p * 16 + lane16) << 7);

    float acc[4][4][4];
    #pragma unroll
    for (int mt = 0; mt < 4; mt++)
        #pragma unroll
        for (int nt = 0; nt < 4; nt++)
            #pragma unroll
            for (int r = 0; r < 4; r++) acc[mt][nt][r] = 0.f;

    const int NC = K >> 6;

    auto issue = [&](int k0, uint32_t sbase) {
        #pragma unroll
        for (int l = 0; l < 4; l++) {
            int gr = bm + cprow[l];
            const __half* ga = A + (size_t)(gr < M ? gr : 0) * K + k0 + cpc[l] * 8;
            cp_async16(sbase + cpsw[l], ga, gr < M ? 16 : 0);
            const __half* gw = W + (size_t)(bn + cprow[l]) * K + k0 + cpc[l] * 8;
            cp_async16(sbase + 16384u + cpsw[l], gw, 16);
        }
    };

    issue(0, smb); CP_COMMIT();
    issue(64, smb + STAGE_BYTES); CP_COMMIT();

    int stage = 0;
    for (int c = 0; c < NC; c++) {
        CP_WAIT1();
        __syncthreads();
        int s2 = stage + 2; if (s2 >= STAGES) s2 -= STAGES;
        if (c + 2 < NC) issue((c + 2) << 6, smb + s2 * STAGE_BYTES);
        CP_COMMIT();

        const uint32_t stb = smb + stage * STAGE_BYTES;
        #pragma unroll
        for (int kk = 0; kk < 4; kk++) {
            uint32_t kb = (uint32_t)(((((kk << 1) | khalf)) ^ rx) << 4);
            uint32_t af[4][4], bf[2][4];
            #pragma unroll
            for (int mt = 0; mt < 4; mt++) ldsm_x4(af[mt], stb + aoff[mt] + kb);
            #pragma unroll
            for (int p = 0; p < 2; p++) ldsm_x4(bf[p], stb + boff[p] + kb);
            #pragma unroll
            for (int mt = 0; mt < 4; mt++) {
                #pragma unroll
                for (int nt = 0; nt < 4; nt++) {
                    int p = nt >> 1, s = nt & 1;
                    uint32_t bb[2] = { bf[p][s], bf[p][2 + s] };
                    mma_f16(acc[mt][nt], af[mt], bb);
                }
            }
        }
        stage = (stage + 1 == STAGES) ? 0 : stage + 1;
    }

    // epilogue
    #pragma unroll
    for (int mt = 0; mt < 4; mt++) {
        int row0 = bm + wm + mt * 16 + gid;
        #pragma unroll
        for (int half_ = 0; half_ < 2; half_++) {
            int row = row0 + half_ * 8;
            if (row >= M) continue;
            #pragma unroll
            for (int nt = 0; nt < 4; nt++) {
                int col = bn + wn + nt * 8 + tig * 2;
                float2 o;
                o.x = acc[mt][nt][half_ * 2 + 0] + bias[col];
                o.y = acc[mt][nt][half_ * 2 + 1] + bias[col + 1];
                if (do_gelu) { o.x = gelu_exact(o.x); o.y = gelu_exact(o.y); }
                if (add) {
                    const float2 a2 = *(const float2*)(add + (size_t)row * Nn + col);
                    o.x += a2.x; o.y += a2.y;
                }
                if (C32) *(float2*)(C32 + (size_t)row * Nn + col) = o;
                if (C16) *(__half2*)(C16 + (size_t)row * Nn + col) = __floats2half2_rn(o.x, o.y);
            }
        }
    }
}

// ---------------- LayerNorm -> fp16 out ----------------
__global__ __launch_bounds__(256) void ln16_kernel(
    const float* __restrict__ X, const float* __restrict__ gg, const float* __restrict__ bb,
    __half* __restrict__ out, int Dg)
{
    size_t row = blockIdx.x;
    const float* x = X + row * (size_t)Dg;
    float s = 0.f, s2 = 0.f;
    for (int i = threadIdx.x; i < Dg; i += 256) {
        float v = x[i];
        s += v; s2 += v * v;
    }
    __shared__ float sh0[8], sh1[8];
    s = warp_sum(s); s2 = warp_sum(s2);
    int w = threadIdx.x >> 5, lane = threadIdx.x & 31;
    if (lane == 0) { sh0[w] = s; sh1[w] = s2; }
    __syncthreads();
    float ts = 0.f, ts2 = 0.f;
    #pragma unroll
    for (int i = 0; i < 8; i++) { ts += sh0[i]; ts2 += sh1[i]; }
    float invD = 1.0f / (float)Dg;
    float mean = ts * invD;
    float rstd = rsqrtf(ts2 * invD - mean * mean + LN_EPS);
    for (int i = threadIdx.x; i < Dg; i += 256)
        out[row * (size_t)Dg + i] = __float2half((x[i] - mean) * rstd * gg[i] + bb[i]);
}

// ---------------- fused attention (fp16 in/out, f32x2 math): 512 thr per (b, h) ----
#define HD 96
#define KPAD 98
#define ATTN_THREADS 512
#define ATTN_WARPS 16
#define ATTN_SMEM ((Nseq * KPAD * 2 + ATTN_WARPS * HD + ATTN_WARPS * 204) * 4)
__global__ __launch_bounds__(ATTN_THREADS) void attn_kernel(
    const __half* __restrict__ QKV, __half* __restrict__ CTX)
{
    extern __shared__ float smf[];
    float* Ks = smf;                              // 197 x 98
    float* Vs = Ks + Nseq * KPAD;                 // 197 x 98
    float* qb = Vs + Nseq * KPAD;                 // 16 x 96
    float* ps = qb + ATTN_WARPS * HD;             // 16 x 204

    int bh = blockIdx.x;
    int b = bh / NHd, h = bh % NHd;
    int tid = threadIdx.x, lane = tid & 31, w = tid >> 5;

    for (int idx = tid; idx < Nseq * HD; idx += ATTN_THREADS) {
        int r = idx / HD, c = idx - r * HD;
        size_t g = (size_t)(b * Nseq + r) * (3 * Dm) + h * HD + c;
        Ks[r * KPAD + c] = __half2float(QKV[g + Dm]);
        Vs[r * KPAD + c] = __half2float(QKV[g + 2 * Dm]);
    }
    __syncthreads();

    const unsigned long long* Ks2 = (const unsigned long long*)Ks;  // stride 49
    const unsigned long long* Vs2 = (const unsigned long long*)Vs;
    const float scl = rsqrtf((float)HD);

    for (int q = w; q < Nseq; q += ATTN_WARPS) {
        for (int d2 = lane; d2 < HD; d2 += 32)
            qb[w * HD + d2] = __half2float(QKV[(size_t)(b * Nseq + q) * (3 * Dm) + h * HD + d2]);
        __syncwarp();

        const unsigned long long* qr2 = (const unsigned long long*)&qb[w * HD]; // 48 pairs
        float s[7];
        float mx = -1e30f;
        #pragma unroll
        for (int jj = 0; jj < 7; jj++) {
            int j = lane + jj * 32;
            float acc = -1e30f;
            if (j < Nseq) {
                unsigned long long a2 = 0ull;
                const unsigned long long* kr2 = Ks2 + (size_t)j * 49;
                #pragma unroll 8
                for (int d2p = 0; d2p < 48; d2p++) a2 = ffma2(qr2[d2p], kr2[d2p], a2);
                float lo, hi; unpack2(a2, lo, hi);
                acc = (lo + hi) * scl;
            }
            s[jj] = acc;
            mx = fmaxf(mx, acc);
        }
        #pragma unroll
        for (int o = 16; o; o >>= 1) mx = fmaxf(mx, __shfl_xor_sync(0xffffffffu, mx, o));
        float sum = 0.f;
        #pragma unroll
        for (int jj = 0; jj < 7; jj++) {
            int j = lane + jj * 32;
            if (j < Nseq) {
                float e = expf(s[jj] - mx);
                ps[w * 204 + j] = e;
                sum += e;
            }
        }
        sum = warp_sum(sum);
        float inv = 1.0f / sum;
        __syncwarp();

        // PV: each lane owns float-pairs d2p, d2p = lane, lane+32 (lane<16)
        const float* pw = &ps[w * 204];
        for (int d2p = lane; d2p < 48; d2p += 32) {
            unsigned long long a2 = 0ull;
            #pragma unroll 4
            for (int j = 0; j < Nseq; j++)
                a2 = ffma2(dup2(pw[j]), Vs2[(size_t)j * 49 + d2p], a2);
            float lo, hi; unpack2(a2, lo, hi);
            size_t o = (size_t)(b * Nseq + q) * Dm + h * HD + 2 * d2p;
            *(__half2*)(CTX + o) = __floats2half2_rn(lo * inv, hi * inv);
        }
        __syncwarp();
    }
}

// ---------------- adapter A: so8 + LN_a + residual + fused LN2 -> fp16 ----------------
__global__ __launch_bounds__(256) void so8ln_a_kernel(
    const float* __restrict__ XP, const float* __restrict__ P, const float* __restrict__ xin,
    const float* __restrict__ eps, const float* __restrict__ scale_p,
    const float* __restrict__ g1, const float* __restrict__ b1,
    const float* __restrict__ g2, const float* __restrict__ b2,
    float* __restrict__ XRES, __half* __restrict__ X2h, float* __restrict__ err)
{
    __shared__ float y[Dm];
    __shared__ float errsum[8];
    __shared__ float sh0[8], sh1[8];
    size_t row = blockIdx.x;
    int tid = threadIdx.x;
    const int hd = Dm / 8;
    if (tid < 8) errsum[tid] = 0.f;
    __syncthreads();
    float scale = scale_p[0];
    const float* xp = XP + row * (size_t)Dm;
    const float* bs = P + row * (size_t)Dm;

    float s = 0.f, s2 = 0.f;
    for (int i = tid; i < Dm; i += 256) {
        int head = i / hd;
        int pos = i - head * hd;
        float v;
        if (pos < 8) {
            int pr = pos >> 1;
            float ang = eps[row * 32 + head * 4 + pr] * scale;
            float sn, c;
            sincosf(ang, &sn, &c);
            float e = xp[head * hd + 2 * pr];
            float o = xp[head * hd + 2 * pr + 1];
            float rot, orig;
            if (pos & 1) { rot = e * sn + o * c; orig = o; }
            else         { rot = e * c - o * sn; orig = e; }
            float d = rot - orig;
            atomicAdd(&errsum[head], d * d);
            v = rot;
        } else v = xp[i];
        v += bs[i];
        y[i] = v;
        s += v; s2 += v * v;
    }
    s = warp_sum(s); s2 = warp_sum(s2);
    int w = tid >> 5, lane = tid & 31;
    if (lane == 0) { sh0[w] = s; sh1[w] = s2; }
    __syncthreads();
    float ts = 0.f, ts2 = 0.f;
    #pragma unroll
    for (int i = 0; i < 8; i++) { ts += sh0[i]; ts2 += sh1[i]; }
    if (tid == 0) {
        float e = 0.f;
        #pragma unroll
        for (int hh = 0; hh < 8; hh++) e += sqrtf(errsum[hh]);
        err[row] = e * 0.125f;
    }
    const float invD = 1.0f / (float)Dm;
    float mean = ts * invD;
    float rstd = rsqrtf(ts2 * invD - mean * mean + LN_EPS);
    __syncthreads();

    s = 0.f; s2 = 0.f;
    for (int i = tid; i < Dm; i += 256) {
        float v = (y[i] - mean) * rstd * g1[i] + b1[i] + bs[i] + xin[row * (size_t)Dm + i];
        XRES[row * (size_t)Dm + i] = v;
        y[i] = v;
        s += v; s2 += v * v;
    }
    s = warp_sum(s); s2 = warp_sum(s2);
    if (lane == 0) { sh0[w] = s; sh1[w] = s2; }
    __syncthreads();
    ts = 0.f; ts2 = 0.f;
    #pragma unroll
    for (int i = 0; i < 8; i++) { ts += sh0[i]; ts2 += sh1[i]; }
    float mean2 = ts * invD;
    float rstd2 = rsqrtf(ts2 * invD - mean2 * mean2 + LN_EPS);
    for (int i = tid; i < Dm; i += 256)
        X2h[row * (size_t)Dm + i] = __float2half((y[i] - mean2) * rstd2 * g2[i] + b2[i]);
}

// ---------------- adapter M: so8 + LN_m + residual -> fp16 ; err tail ----------------
// base H1 now fp16 (H1h)
__global__ __launch_bounds__(256) void so8ln_m_kernel(
    const float* __restrict__ H2, const __half* __restrict__ H1h,
    const float* __restrict__ eps, const float* __restrict__ scale_p,
    const float* __restrict__ gg, const float* __restrict__ bb,
    const float* __restrict__ e1, float* __restrict__ out_tail,
    __half* __restrict__ H3h)
{
    __shared__ float y[HIDm];
    __shared__ float errsum[8];
    __shared__ float sh0[8], sh1[8];
    size_t row = blockIdx.x;
    int tid = threadIdx.x;
    const int hd = HIDm / 8;
    if (tid < 8) errsum[tid] = 0.f;
    __syncthreads();
    float scale = scale_p[0];
    const float* xp = H2 + row * (size_t)HIDm;
    const __half* bsh = H1h + row * (size_t)HIDm;

    float s = 0.f, s2 = 0.f;
    for (int i = tid; i < HIDm; i += 256) {
        int head = i / hd;
        int pos = i - head * hd;
        float v;
        if (pos < 8) {
            int pr = pos >> 1;
            float ang = eps[row * 32 + head * 4 + pr] * scale;
            float sn, c;
            sincosf(ang, &sn, &c);
            float e = xp[head * hd + 2 * pr];
            float o = xp[head * hd + 2 * pr + 1];
            float rot, orig;
            if (pos & 1) { rot = e * sn + o * c; orig = o; }
            else         { rot = e * c - o * sn; orig = e; }
            float d = rot - orig;
            atomicAdd(&errsum[head], d * d);
            v = rot;
        } else v = xp[i];
        v += __half2float(bsh[i]);
        y[i] = v;
        s += v; s2 += v * v;
    }
    s = warp_sum(s); s2 = warp_sum(s2);
    int w = tid >> 5, lane = tid & 31;
    if (lane == 0) { sh0[w] = s; sh1[w] = s2; }
    __syncthreads();
    float ts = 0.f, ts2 = 0.f;
    #pragma unroll
    for (int i = 0; i < 8; i++) { ts += sh0[i]; ts2 += sh1[i]; }
    if (tid == 0) {
        float e = 0.f;
        #pragma unroll
        for (int hh = 0; hh < 8; hh++) e += sqrtf(errsum[hh]);
        out_tail[row] = e * 0.125f + e1[row];
    }
    const float invD = 1.0f / (float)HIDm;
    float mean = ts * invD;
    float rstd = rsqrtf(ts2 * invD - mean * mean + LN_EPS);
    for (int i = tid; i < HIDm; i += 256)
        H3h[row * (size_t)HIDm + i] =
            __float2half((y[i] - mean) * rstd * gg[i] + bb[i] + __half2float(bsh[i]));
}

// ---------------- launch ----------------
extern "C" void kernel_launch(void* const* d_in, const int* in_sizes, int n_in,
                              void* d_out, int out_size)
{
    const float* x       = (const float*)d_in[0];
    const float* qkv_w   = (const float*)d_in[1];
    const float* qkv_b   = (const float*)d_in[2];
    const float* proj_w  = (const float*)d_in[3];
    const float* proj_b  = (const float*)d_in[4];
    const float* norm1_g = (const float*)d_in[5];
    const float* norm1_b = (const float*)d_in[6];
    const float* norm2_g = (const float*)d_in[7];
    const float* norm2_b = (const float*)d_in[8];
    const float* orth_w_a = (const float*)d_in[9];
    const float* orth_b_a = (const float*)d_in[10];
    const float* scale_a  = (const float*)d_in[11];
    const float* ln_g_a   = (const float*)d_in[12];
    const float* ln_b_a   = (const float*)d_in[13];
    const float* orth_w_m = (const float*)d_in[14];
    const float* orth_b_m = (const float*)d_in[15];
    const float* scale_m  = (const float*)d_in[16];
    const float* ln_g_m   = (const float*)d_in[17];
    const float* ln_b_m   = (const float*)d_in[18];
    const float* fc1_w    = (const float*)d_in[19];
    const float* fc1_b    = (const float*)d_in[20];
    const float* fc2_w    = (const float*)d_in[21];
    const float* fc2_b    = (const float*)d_in[22];
    const float* eps_a    = (const float*)d_in[23];
    const float* eps_m    = (const float*)d_in[24];
    float* out = (float*)d_out;

    float *P, *XP, *XRES, *H2, *E1;
    __half *X1h, *QKVh, *CTXh, *Ph, *X2h, *H1h, *H3h;
    __half *WQKVh, *WPROJh, *WOAh, *WOMh, *WF1h, *WF2h;
    cudaGetSymbolAddress((void**)&P,    g_P);
    cudaGetSymbolAddress((void**)&XP,   g_XP);
    cudaGetSymbolAddress((void**)&XRES, g_XRES);
    cudaGetSymbolAddress((void**)&H2,   g_H2);
    cudaGetSymbolAddress((void**)&E1,   g_E1);
    cudaGetSymbolAddress((void**)&X1h,  g_X1h);
    cudaGetSymbolAddress((void**)&QKVh, g_QKVh);
    cudaGetSymbolAddress((void**)&CTXh, g_CTXh);
    cudaGetSymbolAddress((void**)&Ph,   g_Ph);
    cudaGetSymbolAddress((void**)&X2h,  g_X2h);
    cudaGetSymbolAddress((void**)&H1h,  g_H1h);
    cudaGetSymbolAddress((void**)&H3h,  g_H3h);
    cudaGetSymbolAddress((void**)&WQKVh,  g_WQKVh);
    cudaGetSymbolAddress((void**)&WPROJh, g_WPROJh);
    cudaGetSymbolAddress((void**)&WOAh,   g_WOAh);
    cudaGetSymbolAddress((void**)&WOMh,   g_WOMh);
    cudaGetSymbolAddress((void**)&WF1h,   g_WF1h);
    cudaGetSymbolAddress((void**)&WF2h,   g_WF2h);

    cudaFuncSetAttribute(attn_kernel, cudaFuncAttributeMaxDynamicSharedMemorySize, ATTN_SMEM);
    cudaFuncSetAttribute(gemm_tc, cudaFuncAttributeMaxDynamicSharedMemorySize, GEMM_SMEM_BYTES);

    const int MROWS = BNROWS;
    const int GY = (MROWS + 127) / 128;    // 99
    dim3 blk(256);

    // 1) merged fp16 weight prepass (single launch)
    prep_all<<<(CUM5 / 4 + 255) / 256, blk>>>(qkv_w, proj_w, orth_w_a, orth_w_m, fc1_w, fc2_w);
    // 2) x1h = fp16(LN1(x))
    ln16_kernel<<<MROWS, blk>>>(x, norm1_g, norm1_b, X1h, Dm);
    // 3) qkvh = x1 @ qkv_w^T + qkv_b
    gemm_tc<<<dim3(3 * Dm / 128, GY), blk, GEMM_SMEM_BYTES>>>(
        X1h, WQKVh, qkv_b, nullptr, QKVh, nullptr, MROWS, 3 * Dm, Dm, 0);
    // 4) attention -> ctxh
    attn_kernel<<<Bsz * NHd, ATTN_THREADS, ATTN_SMEM>>>(QKVh, CTXh);
    // 5) proj -> P (fp32) + Ph (fp16)
    gemm_tc<<<dim3(Dm / 128, GY), blk, GEMM_SMEM_BYTES>>>(
        CTXh, WPROJh, proj_b, P, Ph, nullptr, MROWS, Dm, Dm, 0);
    // 6) xp = P @ orth_w_a^T + b  [ncu -s 5 captures this launch]
    gemm_tc<<<dim3(Dm / 128, GY), blk, GEMM_SMEM_BYTES>>>(
        Ph, WOAh, orth_b_a, XP, nullptr, nullptr, MROWS, Dm, Dm, 0);
    // 7) adapter A fused: xres (fp32) + x2h (fp16) + err1
    so8ln_a_kernel<<<MROWS, blk>>>(XP, P, x, eps_a, scale_a,
                                   ln_g_a, ln_b_a, norm2_g, norm2_b, XRES, X2h, E1);
    // 8) h1 = gelu(x2 @ fc1^T + b) -> H1h (fp16 only)
    gemm_tc<<<dim3(HIDm / 128, GY), blk, GEMM_SMEM_BYTES>>>(
        X2h, WF1h, fc1_b, nullptr, H1h, nullptr, MROWS, HIDm, Dm, 1);
    // 9) h2 = h1 @ orth_w_m^T + b (fp32)
    gemm_tc<<<dim3(HIDm / 128, GY), blk, GEMM_SMEM_BYTES>>>(
        H1h, WOMh, orth_b_m, H2, nullptr, nullptr, MROWS, HIDm, HIDm, 0);
    // 10) adapter M fused: h3h (fp16) + out tail (e1+e2)
    so8ln_m_kernel<<<MROWS, blk>>>(H2, H1h, eps_m, scale_m, ln_g_m, ln_b_m,
                                   E1, out + (size_t)MROWS * Dm, H3h);
    // 11) out = h3 @ fc2^T + b + xres
    gemm_tc<<<dim3(Dm / 128, GY), blk, GEMM_SMEM_BYTES>>>(
        H3h, WF2h, fc2_b, out, nullptr, XRES, MROWS, Dm, HIDm, 0);
}

// round 12
// speedup vs baseline: 7.3104x; 1.5008x over previous
#include <cuda_runtime.h>
#include <cuda_fp16.h>
#include <math.h>
#include <stdint.h>

// Problem constants
#define Bsz 64
#define Nseq 197
#define Dm 768
#define NHd 8
#define HIDm 3072
#define BNROWS (Bsz * Nseq)          // 12608
#define LN_EPS 1e-5f

// ---------------- scratch (static device arrays; no allocations) ----------------
__device__ __align__(256) float g_P   [BNROWS * Dm];
__device__ __align__(256) float g_XP  [BNROWS * Dm];
__device__ __align__(256) float g_XRES[BNROWS * Dm];
__device__ __align__(256) float g_H2  [BNROWS * HIDm];
__device__ __align__(256) float g_E1  [BNROWS];
// fp16 activation buffers
__device__ __align__(256) __half g_X1h [BNROWS * Dm];
__device__ __align__(256) __half g_QKVh[BNROWS * 3 * Dm];
__device__ __align__(256) __half g_CTXh[BNROWS * Dm];
__device__ __align__(256) __half g_Ph  [BNROWS * Dm];
__device__ __align__(256) __half g_X2h [BNROWS * Dm];
__device__ __align__(256) __half g_H1h [BNROWS * HIDm];
__device__ __align__(256) __half g_H3h [BNROWS * HIDm];
// fp16 weights
__device__ __align__(256) __half g_WQKVh [3 * Dm * Dm];
__device__ __align__(256) __half g_WPROJh[Dm * Dm];
__device__ __align__(256) __half g_WOAh  [Dm * Dm];
__device__ __align__(256) __half g_WOMh  [HIDm * HIDm];
__device__ __align__(256) __half g_WF1h  [HIDm * Dm];
__device__ __align__(256) __half g_WF2h  [Dm * HIDm];

// ---------------- helpers ----------------
__device__ __forceinline__ uint32_t smem_u32(const void* p) {
    uint32_t a;
    asm("{ .reg .u64 t; cvta.to.shared.u64 t, %1; cvt.u32.u64 %0, t; }" : "=r"(a) : "l"(p));
    return a;
}
__device__ __forceinline__ void ldsm_x4(uint32_t* r, uint32_t addr) {
    asm volatile("ldmatrix.sync.aligned.m8n8.x4.shared.b16 {%0,%1,%2,%3}, [%4];"
        : "=r"(r[0]), "=r"(r[1]), "=r"(r[2]), "=r"(r[3]) : "r"(addr));
}
__device__ __forceinline__ void ldsm_x4_t(uint32_t* r, uint32_t addr) {
    asm volatile("ldmatrix.sync.aligned.m8n8.x4.trans.shared.b16 {%0,%1,%2,%3}, [%4];"
        : "=r"(r[0]), "=r"(r[1]), "=r"(r[2]), "=r"(r[3]) : "r"(addr));
}
__device__ __forceinline__ void mma_f16(float* d, const uint32_t* a, uint32_t b0, uint32_t b1) {
    asm volatile("mma.sync.aligned.m16n8k16.row.col.f32.f16.f16.f32 "
        "{%0,%1,%2,%3}, {%4,%5,%6,%7}, {%8,%9}, {%0,%1,%2,%3};"
        : "+f"(d[0]), "+f"(d[1]), "+f"(d[2]), "+f"(d[3])
        : "r"(a[0]), "r"(a[1]), "r"(a[2]), "r"(a[3]), "r"(b0), "r"(b1));
}
__device__ __forceinline__ void cp_async16(uint32_t dst, const void* src, int src_bytes) {
    asm volatile("cp.async.cg.shared.global [%0], [%1], 16, %2;"
                 :: "r"(dst), "l"(src), "r"(src_bytes));
}
#define CP_COMMIT() asm volatile("cp.async.commit_group;" ::: "memory")
#define CP_WAIT1()  asm volatile("cp.async.wait_group 1;" ::: "memory")

__device__ __forceinline__ float warp_sum(float v) {
    #pragma unroll
    for (int o = 16; o; o >>= 1) v += __shfl_xor_sync(0xffffffffu, v, o);
    return v;
}
__device__ __forceinline__ float gelu_exact(float v) {
    return v * 0.5f * (1.0f + erff(v * 0.7071067811865476f));
}

// ---------------- merged weight prepass ----------------
#define SZ_QKV (3 * Dm * Dm)
#define SZ_PRJ (Dm * Dm)
#define SZ_OM  (HIDm * HIDm)
#define SZ_F1  (HIDm * Dm)
#define CUM0 SZ_QKV
#define CUM1 (CUM0 + SZ_PRJ)
#define CUM2 (CUM1 + SZ_PRJ)
#define CUM3 (CUM2 + SZ_OM)
#define CUM4 (CUM3 + SZ_F1)
#define CUM5 (CUM4 + SZ_F1)
__global__ __launch_bounds__(256) void prep_all(
    const float* __restrict__ qkv_w, const float* __restrict__ proj_w,
    const float* __restrict__ orth_a, const float* __restrict__ orth_m,
    const float* __restrict__ fc1_w, const float* __restrict__ fc2_w)
{
    int i = ((int)blockIdx.x * 256 + (int)threadIdx.x) * 4;
    if (i >= CUM5) return;
    const float* src; __half* dst; int off;
    if (i < CUM0)      { src = qkv_w;  dst = g_WQKVh;  off = i; }
    else if (i < CUM1) { src = proj_w; dst = g_WPROJh; off = i - CUM0; }
    else if (i < CUM2) { src = orth_a; dst = g_WOAh;   off = i - CUM1; }
    else if (i < CUM3) { src = orth_m; dst = g_WOMh;   off = i - CUM2; }
    else if (i < CUM4) { src = fc1_w;  dst = g_WF1h;   off = i - CUM3; }
    else               { src = fc2_w;  dst = g_WF2h;   off = i - CUM4; }
    float4 v = *(const float4*)(src + off);
    *(__half2*)(dst + off)     = __floats2half2_rn(v.x, v.y);
    *(__half2*)(dst + off + 2) = __floats2half2_rn(v.z, v.w);
}

// ---------------- fp16 mma.sync GEMM (ldmatrix + cp.async 3-stage) ----------------
#define STAGES 3
#define STAGE_BYTES 32768
#define GEMM_SMEM_BYTES (STAGES * STAGE_BYTES)   // 98304

__global__ void __launch_bounds__(256, 2) gemm_tc(
    const __half* __restrict__ A, const __half* __restrict__ W,
    const float* __restrict__ bias,
    float* __restrict__ C32, __half* __restrict__ C16,
    const float* __restrict__ add,
    int M, int Nn, int K, int do_gelu)
{
    extern __shared__ char smc[];
    const uint32_t smb = smem_u32(smc);

    int tid = threadIdx.x;
    int wid = tid >> 5, lane = tid & 31;
    int gid = lane >> 2, tig = lane & 3;
    int lane16 = lane & 15, khalf = lane >> 4;
    int wm = (wid & 1) * 64;
    int wn = (wid >> 1) * 32;
    int bm = blockIdx.y * 128, bn = blockIdx.x * 128;

    int cprow[4], cpc[4];
    uint32_t cpsw[4];
    #pragma unroll
    for (int l = 0; l < 4; l++) {
        int f = tid + l * 256;
        cprow[l] = f >> 3;
        cpc[l] = f & 7;
        cpsw[l] = ((uint32_t)cprow[l] << 7) | ((uint32_t)((cpc[l] ^ (cprow[l] & 7)) << 4));
    }

    uint32_t rx = (uint32_t)(lane16 & 7);
    uint32_t aoff[4], boff[2];
    #pragma unroll
    for (int mt = 0; mt < 4; mt++) aoff[mt] = (uint32_t)((wm + mt * 16 + lane16) << 7);
    #pragma unroll
    for (int p = 0; p < 2; p++) boff[p] = 16384u + (uint32_t)((wn + p * 16 + lane16) << 7);

    float acc[4][4][4];
    #pragma unroll
    for (int mt = 0; mt < 4; mt++)
        #pragma unroll
        for (int nt = 0; nt < 4; nt++)
            #pragma unroll
            for (int r = 0; r < 4; r++) acc[mt][nt][r] = 0.f;

    const int NC = K >> 6;

    auto issue = [&](int k0, uint32_t sbase) {
        #pragma unroll
        for (int l = 0; l < 4; l++) {
            int gr = bm + cprow[l];
            const __half* ga = A + (size_t)(gr < M ? gr : 0) * K + k0 + cpc[l] * 8;
            cp_async16(sbase + cpsw[l], ga, gr < M ? 16 : 0);
            const __half* gw = W + (size_t)(bn + cprow[l]) * K + k0 + cpc[l] * 8;
            cp_async16(sbase + 16384u + cpsw[l], gw, 16);
        }
    };

    issue(0, smb); CP_COMMIT();
    issue(64, smb + STAGE_BYTES); CP_COMMIT();

    int stage = 0;
    for (int c = 0; c < NC; c++) {
        CP_WAIT1();
        __syncthreads();
        int s2 = stage + 2; if (s2 >= STAGES) s2 -= STAGES;
        if (c + 2 < NC) issue((c + 2) << 6, smb + s2 * STAGE_BYTES);
        CP_COMMIT();

        const uint32_t stb = smb + stage * STAGE_BYTES;
        #pragma unroll
        for (int kk = 0; kk < 4; kk++) {
            uint32_t kb = (uint32_t)(((((kk << 1) | khalf)) ^ rx) << 4);
            uint32_t af[4][4], bf[2][4];
            #pragma unroll
            for (int mt = 0; mt < 4; mt++) ldsm_x4(af[mt], stb + aoff[mt] + kb);
            #pragma unroll
            for (int p = 0; p < 2; p++) ldsm_x4(bf[p], stb + boff[p] + kb);
            #pragma unroll
            for (int mt = 0; mt < 4; mt++) {
                #pragma unroll
                for (int nt = 0; nt < 4; nt++) {
                    int p = nt >> 1, s = nt & 1;
                    mma_f16(acc[mt][nt], af[mt], bf[p][s], bf[p][2 + s]);
                }
            }
        }
        stage = (stage + 1 == STAGES) ? 0 : stage + 1;
    }

    // epilogue
    #pragma unroll
    for (int mt = 0; mt < 4; mt++) {
        int row0 = bm + wm + mt * 16 + gid;
        #pragma unroll
        for (int half_ = 0; half_ < 2; half_++) {
            int row = row0 + half_ * 8;
            if (row >= M) continue;
            #pragma unroll
            for (int nt = 0; nt < 4; nt++) {
                int col = bn + wn + nt * 8 + tig * 2;
                float2 o;
                o.x = acc[mt][nt][half_ * 2 + 0] + bias[col];
                o.y = acc[mt][nt][half_ * 2 + 1] + bias[col + 1];
                if (do_gelu) { o.x = gelu_exact(o.x); o.y = gelu_exact(o.y); }
                if (add) {
                    const float2 a2 = *(const float2*)(add + (size_t)row * Nn + col);
                    o.x += a2.x; o.y += a2.y;
                }
                if (C32) *(float2*)(C32 + (size_t)row * Nn + col) = o;
                if (C16) *(__half2*)(C16 + (size_t)row * Nn + col) = __floats2half2_rn(o.x, o.y);
            }
        }
    }
}

// ---------------- LayerNorm -> fp16 out ----------------
__global__ __launch_bounds__(256) void ln16_kernel(
    const float* __restrict__ X, const float* __restrict__ gg, const float* __restrict__ bb,
    __half* __restrict__ out, int Dg)
{
    size_t row = blockIdx.x;
    const float* x = X + row * (size_t)Dg;
    float s = 0.f, s2 = 0.f;
    for (int i = threadIdx.x; i < Dg; i += 256) {
        float v = x[i];
        s += v; s2 += v * v;
    }
    __shared__ float sh0[8], sh1[8];
    s = warp_sum(s); s2 = warp_sum(s2);
    int w = threadIdx.x >> 5, lane = threadIdx.x & 31;
    if (lane == 0) { sh0[w] = s; sh1[w] = s2; }
    __syncthreads();
    float ts = 0.f, ts2 = 0.f;
    #pragma unroll
    for (int i = 0; i < 8; i++) { ts += sh0[i]; ts2 += sh1[i]; }
    float invD = 1.0f / (float)Dg;
    float mean = ts * invD;
    float rstd = rsqrtf(ts2 * invD - mean * mean + LN_EPS);
    for (int i = threadIdx.x; i < Dg; i += 256)
        out[row * (size_t)Dg + i] = __float2half((x[i] - mean) * rstd * gg[i] + bb[i]);
}

// ---------------- mma flash attention: one block (256 thr) per (b, h) ----------------
// S = Q K^T (m16n8k16), full-row softmax in regs, O = P V via fragment reuse.
#define HD 96
#define KVROWS 208                     // padded to 13 x 16-row tiles (V ldmatrix reads to row 207)
#define KVSTR 104                      // halfs per row (208 B, conflict-free ldmatrix)
#define ATTN_SMEM (2 * KVROWS * KVSTR * 2)   // 86528 B
__global__ void __launch_bounds__(256) attn_kernel(
    const __half* __restrict__ QKV, __half* __restrict__ CTX)
{
    extern __shared__ __half sha[];
    __half* Ksm = sha;                          // [208][104]
    __half* Vsm = sha + KVROWS * KVSTR;         // [208][104]

    int bh = blockIdx.x;
    int b = bh / NHd, h = bh % NHd;
    int tid = threadIdx.x, lane = tid & 31, wid = tid >> 5;
    int gid = lane >> 2, tig = lane & 3;

    // load K, V (fp16, 32b chunks)
    for (int idx = tid; idx < Nseq * 48; idx += 256) {
        int r = idx / 48, c = idx - r * 48;
        size_t g = (size_t)(b * Nseq + r) * (3 * Dm) + h * HD + 2 * c;
        *(uint32_t*)&Ksm[r * KVSTR + 2 * c] = *(const uint32_t*)&QKV[g + Dm];
        *(uint32_t*)&Vsm[r * KVSTR + 2 * c] = *(const uint32_t*)&QKV[g + 2 * Dm];
    }
    // zero padding rows 197..207 (V tile 12 ldmatrix reads rows up to 207)
    for (int idx = tid; idx < (KVROWS - Nseq) * 48; idx += 256) {
        int r = Nseq + idx / 48, c = idx % 48;
        *(uint32_t*)&Ksm[r * KVSTR + 2 * c] = 0;
        *(uint32_t*)&Vsm[r * KVSTR + 2 * c] = 0;
    }
    __syncthreads();

    const uint32_t kbase = smem_u32(Ksm), vbase = smem_u32(Vsm);
    const float scl = rsqrtf((float)HD);

    for (int mt = wid; mt < 13; mt += 8) {
        int bmrow = mt * 16;
        // A fragments (Q) straight from gmem, rows clamped to 196
        int r0 = bmrow + gid;     if (r0 > Nseq - 1) r0 = Nseq - 1;
        int r1 = bmrow + 8 + gid; if (r1 > Nseq - 1) r1 = Nseq - 1;
        size_t ro0 = (size_t)(b * Nseq + r0) * (3 * Dm) + h * HD;
        size_t ro1 = (size_t)(b * Nseq + r1) * (3 * Dm) + h * HD;
        uint32_t aq[6][4];
        #pragma unroll
        for (int kc = 0; kc < 6; kc++) {
            int c0 = kc * 16 + 2 * tig;
            aq[kc][0] = *(const uint32_t*)&QKV[ro0 + c0];
            aq[kc][1] = *(const uint32_t*)&QKV[ro1 + c0];
            aq[kc][2] = *(const uint32_t*)&QKV[ro0 + c0 + 8];
            aq[kc][3] = *(const uint32_t*)&QKV[ro1 + c0 + 8];
        }

        float sacc[25][4];
        #pragma unroll
        for (int jn = 0; jn < 25; jn++)
            #pragma unroll
            for (int r = 0; r < 4; r++) sacc[jn][r] = 0.f;

        // S = Q K^T
        int q4 = lane >> 3;
        #pragma unroll
        for (int jn = 0; jn < 25; jn++) {
            #pragma unroll
            for (int kk = 0; kk < 3; kk++) {
                uint32_t addr = kbase +
                    (uint32_t)(((jn * 8 + (lane & 7)) * KVSTR + kk * 32 + q4 * 8) * 2);
                uint32_t bf[4];
                ldsm_x4(bf, addr);
                mma_f16(sacc[jn], aq[2 * kk],     bf[0], bf[1]);
                mma_f16(sacc[jn], aq[2 * kk + 1], bf[2], bf[3]);
            }
        }

        // mask + scale + softmax (rows gid -> c0,c1 ; gid+8 -> c2,c3)
        float m0 = -1e30f, m1 = -1e30f;
        #pragma unroll
        for (int jn = 0; jn < 25; jn++) {
            int j0 = jn * 8 + 2 * tig;
            sacc[jn][0] = (j0     < Nseq) ? sacc[jn][0] * scl : -1e30f;
            sacc[jn][1] = (j0 + 1 < Nseq) ? sacc[jn][1] * scl : -1e30f;
            sacc[jn][2] = (j0     < Nseq) ? sacc[jn][2] * scl : -1e30f;
            sacc[jn][3] = (j0 + 1 < Nseq) ? sacc[jn][3] * scl : -1e30f;
            m0 = fmaxf(m0, fmaxf(sacc[jn][0], sacc[jn][1]));
            m1 = fmaxf(m1, fmaxf(sacc[jn][2], sacc[jn][3]));
        }
        m0 = fmaxf(m0, __shfl_xor_sync(0xffffffffu, m0, 1));
        m0 = fmaxf(m0, __shfl_xor_sync(0xffffffffu, m0, 2));
        m1 = fmaxf(m1, __shfl_xor_sync(0xffffffffu, m1, 1));
        m1 = fmaxf(m1, __shfl_xor_sync(0xffffffffu, m1, 2));
        float s0 = 0.f, s1 = 0.f;
        #pragma unroll
        for (int jn = 0; jn < 25; jn++) {
            sacc[jn][0] = __expf(sacc[jn][0] - m0);
            sacc[jn][1] = __expf(sacc[jn][1] - m0);
            sacc[jn][2] = __expf(sacc[jn][2] - m1);
            sacc[jn][3] = __expf(sacc[jn][3] - m1);
            s0 += sacc[jn][0] + sacc[jn][1];
            s1 += sacc[jn][2] + sacc[jn][3];
        }
        s0 += __shfl_xor_sync(0xffffffffu, s0, 1);
        s0 += __shfl_xor_sync(0xffffffffu, s0, 2);
        s1 += __shfl_xor_sync(0xffffffffu, s1, 1);
        s1 += __shfl_xor_sync(0xffffffffu, s1, 2);
        float inv0 = 1.0f / s0, inv1 = 1.0f / s1;

        // O = P V
        float oacc[12][4];
        #pragma unroll
        for (int dn = 0; dn < 12; dn++)
            #pragma unroll
            for (int r = 0; r < 4; r++) oacc[dn][r] = 0.f;

        #pragma unroll
        for (int kc2 = 0; kc2 < 13; kc2++) {
            int jn0 = 2 * kc2, jn1 = 2 * kc2 + 1;
            uint32_t p0, p1, p2, p3;
            {
                __half2 t0 = __floats2half2_rn(sacc[jn0][0], sacc[jn0][1]);
                __half2 t1 = __floats2half2_rn(sacc[jn0][2], sacc[jn0][3]);
                p0 = *(uint32_t*)&t0; p1 = *(uint32_t*)&t1;
            }
            if (jn1 < 25) {
                __half2 t2 = __floats2half2_rn(sacc[jn1][0], sacc[jn1][1]);
                __half2 t3 = __floats2half2_rn(sacc[jn1][2], sacc[jn1][3]);
                p2 = *(uint32_t*)&t2; p3 = *(uint32_t*)&t3;
            } else { p2 = 0u; p3 = 0u; }
            uint32_t pfrag[4] = { p0, p1, p2, p3 };

            #pragma unroll
            for (int dn = 0; dn < 12; dn += 2) {
                uint32_t addr = vbase +
                    (uint32_t)(((kc2 * 16 + (q4 & 1) * 8 + (lane & 7)) * KVSTR
                                + dn * 8 + (q4 >> 1) * 8) * 2);
                uint32_t bv[4];
                ldsm_x4_t(bv, addr);
                mma_f16(oacc[dn],     pfrag, bv[0], bv[1]);
                mma_f16(oacc[dn + 1], pfrag, bv[2], bv[3]);
            }
        }

        // store
        int row0 = bmrow + gid, row1 = bmrow + 8 + gid;
        #pragma unroll
        for (int dn = 0; dn < 12; dn++) {
            int d = dn * 8 + 2 * tig;
            if (row0 < Nseq)
                *(__half2*)&CTX[(size_t)(b * Nseq + row0) * Dm + h * HD + d] =
                    __floats2half2_rn(oacc[dn][0] * inv0, oacc[dn][1] * inv0);
            if (row1 < Nseq)
                *(__half2*)&CTX[(size_t)(b * Nseq + row1) * Dm + h * HD + d] =
                    __floats2half2_rn(oacc[dn][2] * inv1, oacc[dn][3] * inv1);
        }
    }
}

// ---------------- adapter A: so8 + LN_a + residual + fused LN2 -> fp16 ----------------
__global__ __launch_bounds__(256) void so8ln_a_kernel(
    const float* __restrict__ XP, const float* __restrict__ P, const float* __restrict__ xin,
    const float* __restrict__ eps, const float* __restrict__ scale_p,
    const float* __restrict__ g1, const float* __restrict__ b1,
    const float* __restrict__ g2, const float* __restrict__ b2,
    float* __restrict__ XRES, __half* __restrict__ X2h, float* __restrict__ err)
{
    __shared__ float y[Dm];
    __shared__ float errsum[8];
    __shared__ float sh0[8], sh1[8];
    size_t row = blockIdx.x;
    int tid = threadIdx.x;
    const int hd = Dm / 8;
    if (tid < 8) errsum[tid] = 0.f;
    __syncthreads();
    float scale = scale_p[0];
    const float* xp = XP + row * (size_t)Dm;
    const float* bs = P + row * (size_t)Dm;

    float s = 0.f, s2 = 0.f;
    for (int i = tid; i < Dm; i += 256) {
        int head = i / hd;
        int pos = i - head * hd;
        float v;
        if (pos < 8) {
            int pr = pos >> 1;
            float ang = eps[row * 32 + head * 4 + pr] * scale;
            float sn, c;
            sincosf(ang, &sn, &c);
            float e = xp[head * hd + 2 * pr];
            float o = xp[head * hd + 2 * pr + 1];
            float rot, orig;
            if (pos & 1) { rot = e * sn + o * c; orig = o; }
            else         { rot = e * c - o * sn; orig = e; }
            float d = rot - orig;
            atomicAdd(&errsum[head], d * d);
            v = rot;
        } else v = xp[i];
        v += bs[i];
        y[i] = v;
        s += v; s2 += v * v;
    }
    s = warp_sum(s); s2 = warp_sum(s2);
    int w = tid >> 5, lane = tid & 31;
    if (lane == 0) { sh0[w] = s; sh1[w] = s2; }
    __syncthreads();
    float ts = 0.f, ts2 = 0.f;
    #pragma unroll
    for (int i = 0; i < 8; i++) { ts += sh0[i]; ts2 += sh1[i]; }
    if (tid == 0) {
        float e = 0.f;
        #pragma unroll
        for (int hh = 0; hh < 8; hh++) e += sqrtf(errsum[hh]);
        err[row] = e * 0.125f;
    }
    const float invD = 1.0f / (float)Dm;
    float mean = ts * invD;
    float rstd = rsqrtf(ts2 * invD - mean * mean + LN_EPS);
    __syncthreads();

    s = 0.f; s2 = 0.f;
    for (int i = tid; i < Dm; i += 256) {
        float v = (y[i] - mean) * rstd * g1[i] + b1[i] + bs[i] + xin[row * (size_t)Dm + i];
        XRES[row * (size_t)Dm + i] = v;
        y[i] = v;
        s += v; s2 += v * v;
    }
    s = warp_sum(s); s2 = warp_sum(s2);
    if (lane == 0) { sh0[w] = s; sh1[w] = s2; }
    __syncthreads();
    ts = 0.f; ts2 = 0.f;
    #pragma unroll
    for (int i = 0; i < 8; i++) { ts += sh0[i]; ts2 += sh1[i]; }
    float mean2 = ts * invD;
    float rstd2 = rsqrtf(ts2 * invD - mean2 * mean2 + LN_EPS);
    for (int i = tid; i < Dm; i += 256)
        X2h[row * (size_t)Dm + i] = __float2half((y[i] - mean2) * rstd2 * g2[i] + b2[i]);
}

// ---------------- adapter M: so8 + LN_m + residual -> fp16 ; err tail ----------------
__global__ __launch_bounds__(256) void so8ln_m_kernel(
    const float* __restrict__ H2, const __half* __restrict__ H1h,
    const float* __restrict__ eps, const float* __restrict__ scale_p,
    const float* __restrict__ gg, const float* __restrict__ bb,
    const float* __restrict__ e1, float* __restrict__ out_tail,
    __half* __restrict__ H3h)
{
    __shared__ float y[HIDm];
    __shared__ float errsum[8];
    __shared__ float sh0[8], sh1[8];
    size_t row = blockIdx.x;
    int tid = threadIdx.x;
    const int hd = HIDm / 8;
    if (tid < 8) errsum[tid] = 0.f;
    __syncthreads();
    float scale = scale_p[0];
    const float* xp = H2 + row * (size_t)HIDm;
    const __half* bsh = H1h + row * (size_t)HIDm;

    float s = 0.f, s2 = 0.f;
    for (int i = tid; i < HIDm; i += 256) {
        int head = i / hd;
        int pos = i - head * hd;
        float v;
        if (pos < 8) {
            int pr = pos >> 1;
            float ang = eps[row * 32 + head * 4 + pr] * scale;
            float sn, c;
            sincosf(ang, &sn, &c);
            float e = xp[head * hd + 2 * pr];
            float o = xp[head * hd + 2 * pr + 1];
            float rot, orig;
            if (pos & 1) { rot = e * sn + o * c; orig = o; }
            else         { rot = e * c - o * sn; orig = e; }
            float d = rot - orig;
            atomicAdd(&errsum[head], d * d);
            v = rot;
        } else v = xp[i];
        v += __half2float(bsh[i]);
        y[i] = v;
        s += v; s2 += v * v;
    }
    s = warp_sum(s); s2 = warp_sum(s2);
    int w = tid >> 5, lane = tid & 31;
    if (lane == 0) { sh0[w] = s; sh1[w] = s2; }
    __syncthreads();
    float ts = 0.f, ts2 = 0.f;
    #pragma unroll
    for (int i = 0; i < 8; i++) { ts += sh0[i]; ts2 += sh1[i]; }
    if (tid == 0) {
        float e = 0.f;
        #pragma unroll
        for (int hh = 0; hh < 8; hh++) e += sqrtf(errsum[hh]);
        out_tail[row] = e * 0.125f + e1[row];
    }
    const float invD = 1.0f / (float)HIDm;
    float mean = ts * invD;
    float rstd = rsqrtf(ts2 * invD - mean * mean + LN_EPS);
    for (int i = tid; i < HIDm; i += 256)
        H3h[row * (size_t)HIDm + i] =
            __float2half((y[i] - mean) * rstd * gg[i] + bb[i] + __half2float(bsh[i]));
}

// ---------------- launch ----------------
extern "C" void kernel_launch(void* const* d_in, const int* in_sizes, int n_in,
                              void* d_out, int out_size)
{
    const float* x       = (const float*)d_in[0];
    const float* qkv_w   = (const float*)d_in[1];
    const float* qkv_b   = (const float*)d_in[2];
    const float* proj_w  = (const float*)d_in[3];
    const float* proj_b  = (const float*)d_in[4];
    const float* norm1_g = (const float*)d_in[5];
    const float* norm1_b = (const float*)d_in[6];
    const float* norm2_g = (const float*)d_in[7];
    const float* norm2_b = (const float*)d_in[8];
    const float* orth_w_a = (const float*)d_in[9];
    const float* orth_b_a = (const float*)d_in[10];
    const float* scale_a  = (const float*)d_in[11];
    const float* ln_g_a   = (const float*)d_in[12];
    const float* ln_b_a   = (const float*)d_in[13];
    const float* orth_w_m = (const float*)d_in[14];
    const float* orth_b_m = (const float*)d_in[15];
    const float* scale_m  = (const float*)d_in[16];
    const float* ln_g_m   = (const float*)d_in[17];
    const float* ln_b_m   = (const float*)d_in[18];
    const float* fc1_w    = (const float*)d_in[19];
    const float* fc1_b    = (const float*)d_in[20];
    const float* fc2_w    = (const float*)d_in[21];
    const float* fc2_b    = (const float*)d_in[22];
    const float* eps_a    = (const float*)d_in[23];
    const float* eps_m    = (const float*)d_in[24];
    float* out = (float*)d_out;

    float *P, *XP, *XRES, *H2, *E1;
    __half *X1h, *QKVh, *CTXh, *Ph, *X2h, *H1h, *H3h;
    __half *WQKVh, *WPROJh, *WOAh, *WOMh, *WF1h, *WF2h;
    cudaGetSymbolAddress((void**)&P,    g_P);
    cudaGetSymbolAddress((void**)&XP,   g_XP);
    cudaGetSymbolAddress((void**)&XRES, g_XRES);
    cudaGetSymbolAddress((void**)&H2,   g_H2);
    cudaGetSymbolAddress((void**)&E1,   g_E1);
    cudaGetSymbolAddress((void**)&X1h,  g_X1h);
    cudaGetSymbolAddress((void**)&QKVh, g_QKVh);
    cudaGetSymbolAddress((void**)&CTXh, g_CTXh);
    cudaGetSymbolAddress((void**)&Ph,   g_Ph);
    cudaGetSymbolAddress((void**)&X2h,  g_X2h);
    cudaGetSymbolAddress((void**)&H1h,  g_H1h);
    cudaGetSymbolAddress((void**)&H3h,  g_H3h);
    cudaGetSymbolAddress((void**)&WQKVh,  g_WQKVh);
    cudaGetSymbolAddress((void**)&WPROJh, g_WPROJh);
    cudaGetSymbolAddress((void**)&WOAh,   g_WOAh);
    cudaGetSymbolAddress((void**)&WOMh,   g_WOMh);
    cudaGetSymbolAddress((void**)&WF1h,   g_WF1h);
    cudaGetSymbolAddress((void**)&WF2h,   g_WF2h);

    cudaFuncSetAttribute(attn_kernel, cudaFuncAttributeMaxDynamicSharedMemorySize, ATTN_SMEM);
    cudaFuncSetAttribute(gemm_tc, cudaFuncAttributeMaxDynamicSharedMemorySize, GEMM_SMEM_BYTES);

    const int MROWS = BNROWS;
    const int GY = (MROWS + 127) / 128;    // 99
    dim3 blk(256);

    // 1) merged fp16 weight prepass
    prep_all<<<(CUM5 / 4 + 255) / 256, blk>>>(qkv_w, proj_w, orth_w_a, orth_w_m, fc1_w, fc2_w);
    // 2) x1h = fp16(LN1(x))
    ln16_kernel<<<MROWS, blk>>>(x, norm1_g, norm1_b, X1h, Dm);
    // 3) qkvh = x1 @ qkv_w^T + qkv_b
    gemm_tc<<<dim3(3 * Dm / 128, GY), blk, GEMM_SMEM_BYTES>>>(
        X1h, WQKVh, qkv_b, nullptr, QKVh, nullptr, MROWS, 3 * Dm, Dm, 0);
    // 4) attention (mma) -> ctxh
    attn_kernel<<<Bsz * NHd, blk, ATTN_SMEM>>>(QKVh, CTXh);
    // 5) proj -> P (fp32) + Ph (fp16)
    gemm_tc<<<dim3(Dm / 128, GY), blk, GEMM_SMEM_BYTES>>>(
        CTXh, WPROJh, proj_b, P, Ph, nullptr, MROWS, Dm, Dm, 0);
    // 6) xp = P @ orth_w_a^T + b
    gemm_tc<<<dim3(Dm / 128, GY), blk, GEMM_SMEM_BYTES>>>(
        Ph, WOAh, orth_b_a, XP, nullptr, nullptr, MROWS, Dm, Dm, 0);
    // 7) adapter A fused
    so8ln_a_kernel<<<MROWS, blk>>>(XP, P, x, eps_a, scale_a,
                                   ln_g_a, ln_b_a, norm2_g, norm2_b, XRES, X2h, E1);
    // 8) h1 = gelu(x2 @ fc1^T + b) -> H1h
    gemm_tc<<<dim3(HIDm / 128, GY), blk, GEMM_SMEM_BYTES>>>(
        X2h, WF1h, fc1_b, nullptr, H1h, nullptr, MROWS, HIDm, Dm, 1);
    // 9) h2 = h1 @ orth_w_m^T + b
    gemm_tc<<<dim3(HIDm / 128, GY), blk, GEMM_SMEM_BYTES>>>(
        H1h, WOMh, orth_b_m, H2, nullptr, nullptr, MROWS, HIDm, HIDm, 0);
    // 10) adapter M fused
    so8ln_m_kernel<<<MROWS, blk>>>(H2, H1h, eps_m, scale_m, ln_g_m, ln_b_m,
                                   E1, out + (size_t)MROWS * Dm, H3h);
    // 11) out = h3 @ fc2^T + b + xres
    gemm_tc<<<dim3(Dm / 128, GY), blk, GEMM_SMEM_BYTES>>>(
        H3h, WF2h, fc2_b, out, nullptr, XRES, MROWS, Dm, HIDm, 0);
}

// round 13
// speedup vs baseline: 7.4763x; 1.0227x over previous
#include <cuda_runtime.h>
#include <cuda_fp16.h>
#include <math.h>
#include <stdint.h>

// Problem constants
#define Bsz 64
#define Nseq 197
#define Dm 768
#define NHd 8
#define HIDm 3072
#define BNROWS (Bsz * Nseq)          // 12608
#define LN_EPS 1e-5f

// ---------------- scratch (static device arrays; no allocations) ----------------
__device__ __align__(256) float g_P   [BNROWS * Dm];
__device__ __align__(256) float g_XP  [BNROWS * Dm];
__device__ __align__(256) float g_XRES[BNROWS * Dm];
__device__ __align__(256) float g_E1  [BNROWS];
// fp16 activation buffers
__device__ __align__(256) __half g_X1h [BNROWS * Dm];
__device__ __align__(256) __half g_QKVh[BNROWS * 3 * Dm];
__device__ __align__(256) __half g_CTXh[BNROWS * Dm];
__device__ __align__(256) __half g_Ph  [BNROWS * Dm];
__device__ __align__(256) __half g_X2h [BNROWS * Dm];
__device__ __align__(256) __half g_H1h [BNROWS * HIDm];
__device__ __align__(256) __half g_H2h [BNROWS * HIDm];
__device__ __align__(256) __half g_H3h [BNROWS * HIDm];
// fp16 weights
__device__ __align__(256) __half g_WQKVh [3 * Dm * Dm];
__device__ __align__(256) __half g_WPROJh[Dm * Dm];
__device__ __align__(256) __half g_WOAh  [Dm * Dm];
__device__ __align__(256) __half g_WOMh  [HIDm * HIDm];
__device__ __align__(256) __half g_WF1h  [HIDm * Dm];
__device__ __align__(256) __half g_WF2h  [Dm * HIDm];

// ---------------- helpers ----------------
__device__ __forceinline__ uint32_t smem_u32(const void* p) {
    uint32_t a;
    asm("{ .reg .u64 t; cvta.to.shared.u64 t, %1; cvt.u32.u64 %0, t; }" : "=r"(a) : "l"(p));
    return a;
}
__device__ __forceinline__ void ldsm_x4(uint32_t* r, uint32_t addr) {
    asm volatile("ldmatrix.sync.aligned.m8n8.x4.shared.b16 {%0,%1,%2,%3}, [%4];"
        : "=r"(r[0]), "=r"(r[1]), "=r"(r[2]), "=r"(r[3]) : "r"(addr));
}
__device__ __forceinline__ void ldsm_x4_t(uint32_t* r, uint32_t addr) {
    asm volatile("ldmatrix.sync.aligned.m8n8.x4.trans.shared.b16 {%0,%1,%2,%3}, [%4];"
        : "=r"(r[0]), "=r"(r[1]), "=r"(r[2]), "=r"(r[3]) : "r"(addr));
}
__device__ __forceinline__ void mma_f16(float* d, const uint32_t* a, uint32_t b0, uint32_t b1) {
    asm volatile("mma.sync.aligned.m16n8k16.row.col.f32.f16.f16.f32 "
        "{%0,%1,%2,%3}, {%4,%5,%6,%7}, {%8,%9}, {%0,%1,%2,%3};"
        : "+f"(d[0]), "+f"(d[1]), "+f"(d[2]), "+f"(d[3])
        : "r"(a[0]), "r"(a[1]), "r"(a[2]), "r"(a[3]), "r"(b0), "r"(b1));
}
__device__ __forceinline__ void cp_async16(uint32_t dst, const void* src, int src_bytes) {
    asm volatile("cp.async.cg.shared.global [%0], [%1], 16, %2;"
                 :: "r"(dst), "l"(src), "r"(src_bytes));
}
#define CP_COMMIT() asm volatile("cp.async.commit_group;" ::: "memory")
#define CP_WAIT1()  asm volatile("cp.async.wait_group 1;" ::: "memory")

__device__ __forceinline__ float warp_sum(float v) {
    #pragma unroll
    for (int o = 16; o; o >>= 1) v += __shfl_xor_sync(0xffffffffu, v, o);
    return v;
}
__device__ __forceinline__ float gelu_exact(float v) {
    return v * 0.5f * (1.0f + erff(v * 0.7071067811865476f));
}

// ---------------- merged weight prepass ----------------
#define SZ_QKV (3 * Dm * Dm)
#define SZ_PRJ (Dm * Dm)
#define SZ_OM  (HIDm * HIDm)
#define SZ_F1  (HIDm * Dm)
#define CUM0 SZ_QKV
#define CUM1 (CUM0 + SZ_PRJ)
#define CUM2 (CUM1 + SZ_PRJ)
#define CUM3 (CUM2 + SZ_OM)
#define CUM4 (CUM3 + SZ_F1)
#define CUM5 (CUM4 + SZ_F1)
__global__ __launch_bounds__(256) void prep_all(
    const float* __restrict__ qkv_w, const float* __restrict__ proj_w,
    const float* __restrict__ orth_a, const float* __restrict__ orth_m,
    const float* __restrict__ fc1_w, const float* __restrict__ fc2_w)
{
    int i = ((int)blockIdx.x * 256 + (int)threadIdx.x) * 4;
    if (i >= CUM5) return;
    const float* src; __half* dst; int off;
    if (i < CUM0)      { src = qkv_w;  dst = g_WQKVh;  off = i; }
    else if (i < CUM1) { src = proj_w; dst = g_WPROJh; off = i - CUM0; }
    else if (i < CUM2) { src = orth_a; dst = g_WOAh;   off = i - CUM1; }
    else if (i < CUM3) { src = orth_m; dst = g_WOMh;   off = i - CUM2; }
    else if (i < CUM4) { src = fc1_w;  dst = g_WF1h;   off = i - CUM3; }
    else               { src = fc2_w;  dst = g_WF2h;   off = i - CUM4; }
    float4 v = *(const float4*)(src + off);
    *(__half2*)(dst + off)     = __floats2half2_rn(v.x, v.y);
    *(__half2*)(dst + off + 2) = __floats2half2_rn(v.z, v.w);
}

// ---------------- fp16 mma.sync GEMM: 128 thr, 4 warps of 64x64, BK=64 ----------------
#define STAGES 3
#define STAGE_BYTES 32768
#define GEMM_SMEM_BYTES (STAGES * STAGE_BYTES)   // 98304

__global__ void __launch_bounds__(128, 2) gemm_tc(
    const __half* __restrict__ A, const __half* __restrict__ W,
    const float* __restrict__ bias,
    float* __restrict__ C32, __half* __restrict__ C16,
    const float* __restrict__ add,
    int M, int Nn, int K, int do_gelu)
{
    extern __shared__ char smc[];
    const uint32_t smb = smem_u32(smc);

    int tid = threadIdx.x;
    int wid = tid >> 5, lane = tid & 31;
    int gid = lane >> 2, tig = lane & 3;
    int lane16 = lane & 15, khalf = lane >> 4;
    int wm = (wid & 1) * 64;
    int wn = (wid >> 1) * 64;
    int bm = blockIdx.y * 128, bn = blockIdx.x * 128;

    // copy coords: per thread 8 A-chunks + 8 B-chunks of 16B
    int cprow[8], cpc[8];
    uint32_t cpsw[8];
    #pragma unroll
    for (int l = 0; l < 8; l++) {
        int f = tid + l * 128;            // 0..1023
        cprow[l] = f >> 3;
        cpc[l] = f & 7;
        cpsw[l] = ((uint32_t)cprow[l] << 7) | ((uint32_t)((cpc[l] ^ (cprow[l] & 7)) << 4));
    }

    uint32_t rx = (uint32_t)(lane16 & 7);
    uint32_t aoff[4], boff[4];
    #pragma unroll
    for (int mt = 0; mt < 4; mt++) aoff[mt] = (uint32_t)((wm + mt * 16 + lane16) << 7);
    #pragma unroll
    for (int p = 0; p < 4; p++) boff[p] = 16384u + (uint32_t)((wn + p * 16 + lane16) << 7);

    float acc[4][8][4];
    #pragma unroll
    for (int mt = 0; mt < 4; mt++)
        #pragma unroll
        for (int nt = 0; nt < 8; nt++)
            #pragma unroll
            for (int r = 0; r < 4; r++) acc[mt][nt][r] = 0.f;

    const int NC = K >> 6;

    auto issue = [&](int k0, uint32_t sbase) {
        #pragma unroll
        for (int l = 0; l < 8; l++) {
            int gr = bm + cprow[l];
            const __half* ga = A + (size_t)(gr < M ? gr : 0) * K + k0 + cpc[l] * 8;
            cp_async16(sbase + cpsw[l], ga, gr < M ? 16 : 0);
            const __half* gw = W + (size_t)(bn + cprow[l]) * K + k0 + cpc[l] * 8;
            cp_async16(sbase + 16384u + cpsw[l], gw, 16);
        }
    };

    issue(0, smb); CP_COMMIT();
    issue(64, smb + STAGE_BYTES); CP_COMMIT();

    int stage = 0;
    for (int c = 0; c < NC; c++) {
        CP_WAIT1();
        __syncthreads();
        int s2 = stage + 2; if (s2 >= STAGES) s2 -= STAGES;
        if (c + 2 < NC) issue((c + 2) << 6, smb + s2 * STAGE_BYTES);
        CP_COMMIT();

        const uint32_t stb = smb + stage * STAGE_BYTES;
        #pragma unroll
        for (int kk = 0; kk < 4; kk++) {
            uint32_t kb = (uint32_t)(((((kk << 1) | khalf)) ^ rx) << 4);
            uint32_t af[4][4], bf[4][4];
            #pragma unroll
            for (int mt = 0; mt < 4; mt++) ldsm_x4(af[mt], stb + aoff[mt] + kb);
            #pragma unroll
            for (int p = 0; p < 4; p++) ldsm_x4(bf[p], stb + boff[p] + kb);
            #pragma unroll
            for (int mt = 0; mt < 4; mt++) {
                #pragma unroll
                for (int nt = 0; nt < 8; nt++) {
                    int p = nt >> 1, s = nt & 1;
                    mma_f16(acc[mt][nt], af[mt], bf[p][s], bf[p][2 + s]);
                }
            }
        }
        stage = (stage + 1 == STAGES) ? 0 : stage + 1;
    }

    // epilogue
    #pragma unroll
    for (int mt = 0; mt < 4; mt++) {
        int row0 = bm + wm + mt * 16 + gid;
        #pragma unroll
        for (int half_ = 0; half_ < 2; half_++) {
            int row = row0 + half_ * 8;
            if (row >= M) continue;
            #pragma unroll
            for (int nt = 0; nt < 8; nt++) {
                int col = bn + wn + nt * 8 + tig * 2;
                float2 o;
                o.x = acc[mt][nt][half_ * 2 + 0] + bias[col];
                o.y = acc[mt][nt][half_ * 2 + 1] + bias[col + 1];
                if (do_gelu) { o.x = gelu_exact(o.x); o.y = gelu_exact(o.y); }
                if (add) {
                    const float2 a2 = *(const float2*)(add + (size_t)row * Nn + col);
                    o.x += a2.x; o.y += a2.y;
                }
                if (C32) *(float2*)(C32 + (size_t)row * Nn + col) = o;
                if (C16) *(__half2*)(C16 + (size_t)row * Nn + col) = __floats2half2_rn(o.x, o.y);
            }
        }
    }
}

// ---------------- LayerNorm -> fp16 out ----------------
__global__ __launch_bounds__(256) void ln16_kernel(
    const float* __restrict__ X, const float* __restrict__ gg, const float* __restrict__ bb,
    __half* __restrict__ out, int Dg)
{
    size_t row = blockIdx.x;
    const float* x = X + row * (size_t)Dg;
    float s = 0.f, s2 = 0.f;
    for (int i = threadIdx.x; i < Dg; i += 256) {
        float v = x[i];
        s += v; s2 += v * v;
    }
    __shared__ float sh0[8], sh1[8];
    s = warp_sum(s); s2 = warp_sum(s2);
    int w = threadIdx.x >> 5, lane = threadIdx.x & 31;
    if (lane == 0) { sh0[w] = s; sh1[w] = s2; }
    __syncthreads();
    float ts = 0.f, ts2 = 0.f;
    #pragma unroll
    for (int i = 0; i < 8; i++) { ts += sh0[i]; ts2 += sh1[i]; }
    float invD = 1.0f / (float)Dg;
    float mean = ts * invD;
    float rstd = rsqrtf(ts2 * invD - mean * mean + LN_EPS);
    for (int i = threadIdx.x; i < Dg; i += 256)
        out[row * (size_t)Dg + i] = __float2half((x[i] - mean) * rstd * gg[i] + bb[i]);
}

// ---------------- mma flash attention: one block (256 thr) per (b, h) ----------------
#define HD 96
#define KVROWS 208
#define KVSTR 104
#define ATTN_SMEM (2 * KVROWS * KVSTR * 2)   // 86528 B
__global__ void __launch_bounds__(256) attn_kernel(
    const __half* __restrict__ QKV, __half* __restrict__ CTX)
{
    extern __shared__ __half sha[];
    __half* Ksm = sha;                          // [208][104]
    __half* Vsm = sha + KVROWS * KVSTR;         // [208][104]

    int bh = blockIdx.x;
    int b = bh / NHd, h = bh % NHd;
    int tid = threadIdx.x, lane = tid & 31, wid = tid >> 5;
    int gid = lane >> 2, tig = lane & 3;

    for (int idx = tid; idx < Nseq * 48; idx += 256) {
        int r = idx / 48, c = idx - r * 48;
        size_t g = (size_t)(b * Nseq + r) * (3 * Dm) + h * HD + 2 * c;
        *(uint32_t*)&Ksm[r * KVSTR + 2 * c] = *(const uint32_t*)&QKV[g + Dm];
        *(uint32_t*)&Vsm[r * KVSTR + 2 * c] = *(const uint32_t*)&QKV[g + 2 * Dm];
    }
    for (int idx = tid; idx < (KVROWS - Nseq) * 48; idx += 256) {
        int r = Nseq + idx / 48, c = idx % 48;
        *(uint32_t*)&Ksm[r * KVSTR + 2 * c] = 0;
        *(uint32_t*)&Vsm[r * KVSTR + 2 * c] = 0;
    }
    __syncthreads();

    const uint32_t kbase = smem_u32(Ksm), vbase = smem_u32(Vsm);
    const float scl = rsqrtf((float)HD);

    for (int mt = wid; mt < 13; mt += 8) {
        int bmrow = mt * 16;
        int r0 = bmrow + gid;     if (r0 > Nseq - 1) r0 = Nseq - 1;
        int r1 = bmrow + 8 + gid; if (r1 > Nseq - 1) r1 = Nseq - 1;
        size_t ro0 = (size_t)(b * Nseq + r0) * (3 * Dm) + h * HD;
        size_t ro1 = (size_t)(b * Nseq + r1) * (3 * Dm) + h * HD;
        uint32_t aq[6][4];
        #pragma unroll
        for (int kc = 0; kc < 6; kc++) {
            int c0 = kc * 16 + 2 * tig;
            aq[kc][0] = *(const uint32_t*)&QKV[ro0 + c0];
            aq[kc][1] = *(const uint32_t*)&QKV[ro1 + c0];
            aq[kc][2] = *(const uint32_t*)&QKV[ro0 + c0 + 8];
            aq[kc][3] = *(const uint32_t*)&QKV[ro1 + c0 + 8];
        }

        float sacc[25][4];
        #pragma unroll
        for (int jn = 0; jn < 25; jn++)
            #pragma unroll
            for (int r = 0; r < 4; r++) sacc[jn][r] = 0.f;

        int q4 = lane >> 3;
        #pragma unroll
        for (int jn = 0; jn < 25; jn++) {
            #pragma unroll
            for (int kk = 0; kk < 3; kk++) {
                uint32_t addr = kbase +
                    (uint32_t)(((jn * 8 + (lane & 7)) * KVSTR + kk * 32 + q4 * 8) * 2);
                uint32_t bf[4];
                ldsm_x4(bf, addr);
                mma_f16(sacc[jn], aq[2 * kk],     bf[0], bf[1]);
                mma_f16(sacc[jn], aq[2 * kk + 1], bf[2], bf[3]);
            }
        }

        float m0 = -1e30f, m1 = -1e30f;
        #pragma unroll
        for (int jn = 0; jn < 25; jn++) {
            int j0 = jn * 8 + 2 * tig;
            sacc[jn][0] = (j0     < Nseq) ? sacc[jn][0] * scl : -1e30f;
            sacc[jn][1] = (j0 + 1 < Nseq) ? sacc[jn][1] * scl : -1e30f;
            sacc[jn][2] = (j0     < Nseq) ? sacc[jn][2] * scl : -1e30f;
            sacc[jn][3] = (j0 + 1 < Nseq) ? sacc[jn][3] * scl : -1e30f;
            m0 = fmaxf(m0, fmaxf(sacc[jn][0], sacc[jn][1]));
            m1 = fmaxf(m1, fmaxf(sacc[jn][2], sacc[jn][3]));
        }
        m0 = fmaxf(m0, __shfl_xor_sync(0xffffffffu, m0, 1));
        m0 = fmaxf(m0, __shfl_xor_sync(0xffffffffu, m0, 2));
        m1 = fmaxf(m1, __shfl_xor_sync(0xffffffffu, m1, 1));
        m1 = fmaxf(m1, __shfl_xor_sync(0xffffffffu, m1, 2));
        float s0 = 0.f, s1 = 0.f;
        #pragma unroll
        for (int jn = 0; jn < 25; jn++) {
            sacc[jn][0] = __expf(sacc[jn][0] - m0);
            sacc[jn][1] = __expf(sacc[jn][1] - m0);
            sacc[jn][2] = __expf(sacc[jn][2] - m1);
            sacc[jn][3] = __expf(sacc[jn][3] - m1);
            s0 += sacc[jn][0] + sacc[jn][1];
            s1 += sacc[jn][2] + sacc[jn][3];
        }
        s0 += __shfl_xor_sync(0xffffffffu, s0, 1);
        s0 += __shfl_xor_sync(0xffffffffu, s0, 2);
        s1 += __shfl_xor_sync(0xffffffffu, s1, 1);
        s1 += __shfl_xor_sync(0xffffffffu, s1, 2);
        float inv0 = 1.0f / s0, inv1 = 1.0f / s1;

        float oacc[12][4];
        #pragma unroll
        for (int dn = 0; dn < 12; dn++)
            #pragma unroll
            for (int r = 0; r < 4; r++) oacc[dn][r] = 0.f;

        #pragma unroll
        for (int kc2 = 0; kc2 < 13; kc2++) {
            int jn0 = 2 * kc2, jn1 = 2 * kc2 + 1;
            uint32_t p0, p1, p2, p3;
            {
                __half2 t0 = __floats2half2_rn(sacc[jn0][0], sacc[jn0][1]);
                __half2 t1 = __floats2half2_rn(sacc[jn0][2], sacc[jn0][3]);
                p0 = *(uint32_t*)&t0; p1 = *(uint32_t*)&t1;
            }
            if (jn1 < 25) {
                __half2 t2 = __floats2half2_rn(sacc[jn1][0], sacc[jn1][1]);
                __half2 t3 = __floats2half2_rn(sacc[jn1][2], sacc[jn1][3]);
                p2 = *(uint32_t*)&t2; p3 = *(uint32_t*)&t3;
            } else { p2 = 0u; p3 = 0u; }
            uint32_t pfrag[4] = { p0, p1, p2, p3 };

            #pragma unroll
            for (int dn = 0; dn < 12; dn += 2) {
                uint32_t addr = vbase +
                    (uint32_t)(((kc2 * 16 + (q4 & 1) * 8 + (lane & 7)) * KVSTR
                                + dn * 8 + (q4 >> 1) * 8) * 2);
                uint32_t bv[4];
                ldsm_x4_t(bv, addr);
                mma_f16(oacc[dn],     pfrag, bv[0], bv[1]);
                mma_f16(oacc[dn + 1], pfrag, bv[2], bv[3]);
            }
        }

        int row0 = bmrow + gid, row1 = bmrow + 8 + gid;
        #pragma unroll
        for (int dn = 0; dn < 12; dn++) {
            int d = dn * 8 + 2 * tig;
            if (row0 < Nseq)
                *(__half2*)&CTX[(size_t)(b * Nseq + row0) * Dm + h * HD + d] =
                    __floats2half2_rn(oacc[dn][0] * inv0, oacc[dn][1] * inv0);
            if (row1 < Nseq)
                *(__half2*)&CTX[(size_t)(b * Nseq + row1) * Dm + h * HD + d] =
                    __floats2half2_rn(oacc[dn][2] * inv1, oacc[dn][3] * inv1);
        }
    }
}

// ---------------- adapter A: so8 + LN_a + residual + fused LN2 -> fp16 ----------------
__global__ __launch_bounds__(256) void so8ln_a_kernel(
    const float* __restrict__ XP, const float* __restrict__ P, const float* __restrict__ xin,
    const float* __restrict__ eps, const float* __restrict__ scale_p,
    const float* __restrict__ g1, const float* __restrict__ b1,
    const float* __restrict__ g2, const float* __restrict__ b2,
    float* __restrict__ XRES, __half* __restrict__ X2h, float* __restrict__ err)
{
    __shared__ float y[Dm];
    __shared__ float errsum[8];
    __shared__ float sh0[8], sh1[8];
    size_t row = blockIdx.x;
    int tid = threadIdx.x;
    const int hd = Dm / 8;
    if (tid < 8) errsum[tid] = 0.f;
    __syncthreads();
    float scale = scale_p[0];
    const float* xp = XP + row * (size_t)Dm;
    const float* bs = P + row * (size_t)Dm;

    float s = 0.f, s2 = 0.f;
    for (int i = tid; i < Dm; i += 256) {
        int head = i / hd;
        int pos = i - head * hd;
        float v;
        if (pos < 8) {
            int pr = pos >> 1;
            float ang = eps[row * 32 + head * 4 + pr] * scale;
            float sn, c;
            sincosf(ang, &sn, &c);
            float e = xp[head * hd + 2 * pr];
            float o = xp[head * hd + 2 * pr + 1];
            float rot, orig;
            if (pos & 1) { rot = e * sn + o * c; orig = o; }
            else         { rot = e * c - o * sn; orig = e; }
            float d = rot - orig;
            atomicAdd(&errsum[head], d * d);
            v = rot;
        } else v = xp[i];
        v += bs[i];
        y[i] = v;
        s += v; s2 += v * v;
    }
    s = warp_sum(s); s2 = warp_sum(s2);
    int w = tid >> 5, lane = tid & 31;
    if (lane == 0) { sh0[w] = s; sh1[w] = s2; }
    __syncthreads();
    float ts = 0.f, ts2 = 0.f;
    #pragma unroll
    for (int i = 0; i < 8; i++) { ts += sh0[i]; ts2 += sh1[i]; }
    if (tid == 0) {
        float e = 0.f;
        #pragma unroll
        for (int hh = 0; hh < 8; hh++) e += sqrtf(errsum[hh]);
        err[row] = e * 0.125f;
    }
    const float invD = 1.0f / (float)Dm;
    float mean = ts * invD;
    float rstd = rsqrtf(ts2 * invD - mean * mean + LN_EPS);
    __syncthreads();

    s = 0.f; s2 = 0.f;
    for (int i = tid; i < Dm; i += 256) {
        float v = (y[i] - mean) * rstd * g1[i] + b1[i] + bs[i] + xin[row * (size_t)Dm + i];
        XRES[row * (size_t)Dm + i] = v;
        y[i] = v;
        s += v; s2 += v * v;
    }
    s = warp_sum(s); s2 = warp_sum(s2);
    if (lane == 0) { sh0[w] = s; sh1[w] = s2; }
    __syncthreads();
    ts = 0.f; ts2 = 0.f;
    #pragma unroll
    for (int i = 0; i < 8; i++) { ts += sh0[i]; ts2 += sh1[i]; }
    float mean2 = ts * invD;
    float rstd2 = rsqrtf(ts2 * invD - mean2 * mean2 + LN_EPS);
    for (int i = tid; i < Dm; i += 256)
        X2h[row * (size_t)Dm + i] = __float2half((y[i] - mean2) * rstd2 * g2[i] + b2[i]);
}

// ---------------- adapter M: so8 + LN_m + residual -> fp16 ; err tail ----------------
// H2 now fp16 (H2h)
__global__ __launch_bounds__(256) void so8ln_m_kernel(
    const __half* __restrict__ H2h, const __half* __restrict__ H1h,
    const float* __restrict__ eps, const float* __restrict__ scale_p,
    const float* __restrict__ gg, const float* __restrict__ bb,
    const float* __restrict__ e1, float* __restrict__ out_tail,
    __half* __restrict__ H3h)
{
    __shared__ float y[HIDm];
    __shared__ float errsum[8];
    __shared__ float sh0[8], sh1[8];
    size_t row = blockIdx.x;
    int tid = threadIdx.x;
    const int hd = HIDm / 8;
    if (tid < 8) errsum[tid] = 0.f;
    __syncthreads();
    float scale = scale_p[0];
    const __half* xph = H2h + row * (size_t)HIDm;
    const __half* bsh = H1h + row * (size_t)HIDm;

    float s = 0.f, s2 = 0.f;
    for (int i = tid; i < HIDm; i += 256) {
        int head = i / hd;
        int pos = i - head * hd;
        float v;
        if (pos < 8) {
            int pr = pos >> 1;
            float ang = eps[row * 32 + head * 4 + pr] * scale;
            float sn, c;
            sincosf(ang, &sn, &c);
            float e = __half2float(xph[head * hd + 2 * pr]);
            float o = __half2float(xph[head * hd + 2 * pr + 1]);
            float rot, orig;
            if (pos & 1) { rot = e * sn + o * c; orig = o; }
            else         { rot = e * c - o * sn; orig = e; }
            float d = rot - orig;
            atomicAdd(&errsum[head], d * d);
            v = rot;
        } else v = __half2float(xph[i]);
        v += __half2float(bsh[i]);
        y[i] = v;
        s += v; s2 += v * v;
    }
    s = warp_sum(s); s2 = warp_sum(s2);
    int w = tid >> 5, lane = tid & 31;
    if (lane == 0) { sh0[w] = s; sh1[w] = s2; }
    __syncthreads();
    float ts = 0.f, ts2 = 0.f;
    #pragma unroll
    for (int i = 0; i < 8; i++) { ts += sh0[i]; ts2 += sh1[i]; }
    if (tid == 0) {
        float e = 0.f;
        #pragma unroll
        for (int hh = 0; hh < 8; hh++) e += sqrtf(errsum[hh]);
        out_tail[row] = e * 0.125f + e1[row];
    }
    const float invD = 1.0f / (float)HIDm;
    float mean = ts * invD;
    float rstd = rsqrtf(ts2 * invD - mean * mean + LN_EPS);
    for (int i = tid; i < HIDm; i += 256)
        H3h[row * (size_t)HIDm + i] =
            __float2half((y[i] - mean) * rstd * gg[i] + bb[i] + __half2float(bsh[i]));
}

// ---------------- launch ----------------
extern "C" void kernel_launch(void* const* d_in, const int* in_sizes, int n_in,
                              void* d_out, int out_size)
{
    const float* x       = (const float*)d_in[0];
    const float* qkv_w   = (const float*)d_in[1];
    const float* qkv_b   = (const float*)d_in[2];
    const float* proj_w  = (const float*)d_in[3];
    const float* proj_b  = (const float*)d_in[4];
    const float* norm1_g = (const float*)d_in[5];
    const float* norm1_b = (const float*)d_in[6];
    const float* norm2_g = (const float*)d_in[7];
    const float* norm2_b = (const float*)d_in[8];
    const float* orth_w_a = (const float*)d_in[9];
    const float* orth_b_a = (const float*)d_in[10];
    const float* scale_a  = (const float*)d_in[11];
    const float* ln_g_a   = (const float*)d_in[12];
    const float* ln_b_a   = (const float*)d_in[13];
    const float* orth_w_m = (const float*)d_in[14];
    const float* orth_b_m = (const float*)d_in[15];
    const float* scale_m  = (const float*)d_in[16];
    const float* ln_g_m   = (const float*)d_in[17];
    const float* ln_b_m   = (const float*)d_in[18];
    const float* fc1_w    = (const float*)d_in[19];
    const float* fc1_b    = (const float*)d_in[20];
    const float* fc2_w    = (const float*)d_in[21];
    const float* fc2_b    = (const float*)d_in[22];
    const float* eps_a    = (const float*)d_in[23];
    const float* eps_m    = (const float*)d_in[24];
    float* out = (float*)d_out;

    float *P, *XP, *XRES, *E1;
    __half *X1h, *QKVh, *CTXh, *Ph, *X2h, *H1h, *H2h, *H3h;
    __half *WQKVh, *WPROJh, *WOAh, *WOMh, *WF1h, *WF2h;
    cudaGetSymbolAddress((void**)&P,    g_P);
    cudaGetSymbolAddress((void**)&XP,   g_XP);
    cudaGetSymbolAddress((void**)&XRES, g_XRES);
    cudaGetSymbolAddress((void**)&E1,   g_E1);
    cudaGetSymbolAddress((void**)&X1h,  g_X1h);
    cudaGetSymbolAddress((void**)&QKVh, g_QKVh);
    cudaGetSymbolAddress((void**)&CTXh, g_CTXh);
    cudaGetSymbolAddress((void**)&Ph,   g_Ph);
    cudaGetSymbolAddress((void**)&X2h,  g_X2h);
    cudaGetSymbolAddress((void**)&H1h,  g_H1h);
    cudaGetSymbolAddress((void**)&H2h,  g_H2h);
    cudaGetSymbolAddress((void**)&H3h,  g_H3h);
    cudaGetSymbolAddress((void**)&WQKVh,  g_WQKVh);
    cudaGetSymbolAddress((void**)&WPROJh, g_WPROJh);
    cudaGetSymbolAddress((void**)&WOAh,   g_WOAh);
    cudaGetSymbolAddress((void**)&WOMh,   g_WOMh);
    cudaGetSymbolAddress((void**)&WF1h,   g_WF1h);
    cudaGetSymbolAddress((void**)&WF2h,   g_WF2h);

    cudaFuncSetAttribute(attn_kernel, cudaFuncAttributeMaxDynamicSharedMemorySize, ATTN_SMEM);
    cudaFuncSetAttribute(gemm_tc, cudaFuncAttributeMaxDynamicSharedMemorySize, GEMM_SMEM_BYTES);

    const int MROWS = BNROWS;
    const int GY = (MROWS + 127) / 128;    // 99
    dim3 blk256(256);
    dim3 blk128(128);

    // 1) merged fp16 weight prepass
    prep_all<<<(CUM5 / 4 + 255) / 256, blk256>>>(qkv_w, proj_w, orth_w_a, orth_w_m, fc1_w, fc2_w);
    // 2) x1h = fp16(LN1(x))
    ln16_kernel<<<MROWS, blk256>>>(x, norm1_g, norm1_b, X1h, Dm);
    // 3) qkvh = x1 @ qkv_w^T + qkv_b
    gemm_tc<<<dim3(3 * Dm / 128, GY), blk128, GEMM_SMEM_BYTES>>>(
        X1h, WQKVh, qkv_b, nullptr, QKVh, nullptr, MROWS, 3 * Dm, Dm, 0);
    // 4) attention (mma) -> ctxh
    attn_kernel<<<Bsz * NHd, blk256, ATTN_SMEM>>>(QKVh, CTXh);
    // 5) proj -> P (fp32) + Ph (fp16)
    gemm_tc<<<dim3(Dm / 128, GY), blk128, GEMM_SMEM_BYTES>>>(
        CTXh, WPROJh, proj_b, P, Ph, nullptr, MROWS, Dm, Dm, 0);
    // 6) xp = P @ orth_w_a^T + b
    gemm_tc<<<dim3(Dm / 128, GY), blk128, GEMM_SMEM_BYTES>>>(
        Ph, WOAh, orth_b_a, XP, nullptr, nullptr, MROWS, Dm, Dm, 0);
    // 7) adapter A fused
    so8ln_a_kernel<<<MROWS, blk256>>>(XP, P, x, eps_a, scale_a,
                                      ln_g_a, ln_b_a, norm2_g, norm2_b, XRES, X2h, E1);
    // 8) h1 = gelu(x2 @ fc1^T + b) -> H1h
    gemm_tc<<<dim3(HIDm / 128, GY), blk128, GEMM_SMEM_BYTES>>>(
        X2h, WF1h, fc1_b, nullptr, H1h, nullptr, MROWS, HIDm, Dm, 1);
    // 9) h2 = h1 @ orth_w_m^T + b -> H2h (fp16 only)
    gemm_tc<<<dim3(HIDm / 128, GY), blk128, GEMM_SMEM_BYTES>>>(
        H1h, WOMh, orth_b_m, nullptr, H2h, nullptr, MROWS, HIDm, HIDm, 0);
    // 10) adapter M fused
    so8ln_m_kernel<<<MROWS, blk256>>>(H2h, H1h, eps_m, scale_m, ln_g_m, ln_b_m,
                                      E1, out + (size_t)MROWS * Dm, H3h);
    // 11) out = h3 @ fc2^T + b + xres
    gemm_tc<<<dim3(Dm / 128, GY), blk128, GEMM_SMEM_BYTES>>>(
        H3h, WF2h, fc2_b, out, nullptr, XRES, MROWS, Dm, HIDm, 0);
}